// round 1
// baseline (speedup 1.0000x reference)
#include <cuda_runtime.h>
#include <cstdint>

// Problem constants (fixed shapes from reference)
#define NHEAD 8
#define DH    64
#define AWIN  64        // window area (8x8)
#define HW_   128       // H = W = 128
#define NB    4         // batch
#define NPIX  65536     // B*H*W
#define CCH   512       // channels = NHEAD*DH

// Scratch: attention output in [c][b*16384 + h*128 + w] layout (GEMM-friendly)
__device__ float g_xbuf[(size_t)CCH * NPIX];
// Precomputed relative position bias: [head][ka][qa]
__device__ float g_bias[NHEAD * AWIN * AWIN];

// ---------------------------------------------------------------------------
// Kernel 0: expand rpb_table via rel_index into [h][ka][qa]
// ---------------------------------------------------------------------------
__global__ void bias_kernel(const float* __restrict__ rpb, const int* __restrict__ rel) {
    int idx = blockIdx.x * blockDim.x + threadIdx.x;
    if (idx >= NHEAD * AWIN * AWIN) return;
    int h  = idx >> 12;          // / 4096
    int r  = idx & 4095;
    int ka = r >> 6;
    int qa = r & 63;
    g_bias[idx] = rpb[rel[qa * AWIN + ka] * NHEAD + h];
}

// ---------------------------------------------------------------------------
// Kernel 1: windowed cosine attention.
// One block = one (window, head). 64 threads, thread t = query row t.
// smem layout [d][a] (d slow, a fast): column reads conflict-free,
// row reads are warp-broadcast.
// ---------------------------------------------------------------------------
__global__ void __launch_bounds__(64) attn_kernel(const float* __restrict__ qkv,
                                                  const float* __restrict__ lscale) {
    __shared__ float sm[3 * 4096];     // 48 KB: q | k | v, each [64][64]
    float* sq = sm;
    float* sk = sm + 4096;
    float* sv = sm + 8192;

    const int t    = threadIdx.x;      // query index / own k,v column
    const int wh   = blockIdx.x;
    const int head = wh & 7;
    const int win  = wh >> 3;
    const int b    = win >> 8;
    const int wy   = (win >> 4) & 15;
    const int wx   = win & 15;

    // qkv: (B, Hh, 192, 128, 128) row-major
    const float* base = qkv + (size_t)b * (NHEAD * 192 * 16384)
                            + (size_t)head * (192 * 16384)
                            + wy * 8 * HW_ + wx * 8;

    // Cooperative load: iteration it == channel d, lane t == window pixel a.
    // Per-warp access = 4 rows of 8 contiguous floats (full 32B sectors).
    const int aoff = ((t >> 3) * HW_) + (t & 7);
    #pragma unroll 4
    for (int d = 0; d < 64; d++) {
        int off = d * 16384 + aoff;
        sq[d * 64 + t] = base[off];
        sk[d * 64 + t] = base[off +  64 * 16384];
        sv[d * 64 + t] = base[off + 128 * 16384];
    }
    __syncthreads();

    const float sc = __expf(fminf(lscale[head], 4.6051702f));   // log(100)

    // Normalize own q column (fold in scale) and own k column, in place.
    float q0 = 0.f, q1 = 0.f;
    #pragma unroll 8
    for (int d = 0; d < 64; d += 2) {
        float a = sq[d * 64 + t], bq = sq[(d + 1) * 64 + t];
        q0 += a * a; q1 += bq * bq;
    }
    const float invq = sc / fmaxf(sqrtf(q0 + q1), 1e-12f);
    #pragma unroll 8
    for (int d = 0; d < 64; d++) sq[d * 64 + t] *= invq;

    float k0 = 0.f, k1 = 0.f;
    #pragma unroll 8
    for (int d = 0; d < 64; d += 2) {
        float a = sk[d * 64 + t], bk = sk[(d + 1) * 64 + t];
        k0 += a * a; k1 += bk * bk;
    }
    const float invk = 1.0f / fmaxf(sqrtf(k0 + k1), 1e-12f);
    #pragma unroll 8
    for (int d = 0; d < 64; d++) sk[d * 64 + t] *= invk;
    __syncthreads();   // everyone reads all k columns next

    // Logits: p[ka] = sum_d q[t][d] * k[ka][d]. 64 independent accumulators.
    float p[64];
    #pragma unroll
    for (int i = 0; i < 64; i++) p[i] = 0.f;

    const float4* sk4 = (const float4*)sk;
    for (int d = 0; d < 64; d++) {
        float qv = sq[d * 64 + t];               // own column, conflict-free
        #pragma unroll
        for (int g = 0; g < 16; g++) {
            float4 kv = sk4[d * 16 + g];         // broadcast LDS.128
            p[4 * g + 0] += qv * kv.x;
            p[4 * g + 1] += qv * kv.y;
            p[4 * g + 2] += qv * kv.z;
            p[4 * g + 3] += qv * kv.w;
        }
    }

    // + relative position bias (coalesced global, L2-resident 128KB table)
    const float* gb = g_bias + head * 4096;
    #pragma unroll
    for (int i = 0; i < 64; i++) p[i] += gb[i * 64 + t];

    // Softmax over ka (whole row lives in this thread)
    float m = p[0];
    #pragma unroll
    for (int i = 1; i < 64; i++) m = fmaxf(m, p[i]);
    float s0 = 0.f, s1 = 0.f, s2 = 0.f, s3 = 0.f;
    #pragma unroll
    for (int i = 0; i < 64; i += 4) {
        p[i + 0] = __expf(p[i + 0] - m); s0 += p[i + 0];
        p[i + 1] = __expf(p[i + 1] - m); s1 += p[i + 1];
        p[i + 2] = __expf(p[i + 2] - m); s2 += p[i + 2];
        p[i + 3] = __expf(p[i + 3] - m); s3 += p[i + 3];
    }
    const float inv = 1.0f / ((s0 + s1) + (s2 + s3));
    #pragma unroll
    for (int i = 0; i < 64; i++) p[i] *= inv;

    // PV: out[t][d] = sum_a p[a] * v[a][d]; store straight to scratch.
    const int pixbase = b * 16384 + (wy * 8 + (t >> 3)) * HW_ + wx * 8 + (t & 7);
    float* xb = g_xbuf + (size_t)(head * DH) * NPIX + pixbase;
    const float4* sv4 = (const float4*)sv;
    for (int d = 0; d < 64; d++) {
        float a0 = 0.f, a1 = 0.f, a2 = 0.f, a3 = 0.f;
        #pragma unroll
        for (int g = 0; g < 16; g++) {
            float4 vv = sv4[d * 16 + g];         // broadcast LDS.128
            a0 += p[4 * g + 0] * vv.x;
            a1 += p[4 * g + 1] * vv.y;
            a2 += p[4 * g + 2] * vv.z;
            a3 += p[4 * g + 3] * vv.w;
        }
        xb[(size_t)d * NPIX] = (a0 + a1) + (a2 + a3);
    }
}

// ---------------------------------------------------------------------------
// Kernel 2: projection GEMM.  out[M=512][N=65536] = W[512][512] @ X[512][65536] + b
// Classic 128x128x8 SGEMM, 256 threads, 8x8 per thread (2x2 quads of 4x4).
// Output index: n = b*16384 + hw -> out[(b*512 + m)*16384 + hw].
// ---------------------------------------------------------------------------
__global__ void __launch_bounds__(256) proj_kernel(const float* __restrict__ W,
                                                   const float* __restrict__ pb,
                                                   float* __restrict__ out) {
    __shared__ float As[8][128];   // A transposed: As[k][m]
    __shared__ float Bs[8][128];

    const int tid = threadIdx.x;
    const int m0  = blockIdx.y * 128;
    const int n0  = blockIdx.x * 128;
    const int tm  = tid >> 4;       // 0..15
    const int tn  = tid & 15;       // 0..15

    float acc[8][8];
    #pragma unroll
    for (int i = 0; i < 8; i++)
        #pragma unroll
        for (int j = 0; j < 8; j++) acc[i][j] = 0.f;

    const int arow = tid >> 1;             // 0..127
    const int acol = (tid & 1) * 4;        // 0 or 4
    const int brow = tid >> 5;             // 0..7
    const int bcol = (tid & 31) * 4;

    const float* Ap = W + (m0 + arow) * CCH + acol;
    const float* Bp = g_xbuf + (size_t)brow * NPIX + n0 + bcol;

    for (int kk0 = 0; kk0 < CCH; kk0 += 8) {
        float4 av = *(const float4*)(Ap + kk0);
        float4 bv = *(const float4*)(Bp + (size_t)kk0 * NPIX);
        As[acol + 0][arow] = av.x;
        As[acol + 1][arow] = av.y;
        As[acol + 2][arow] = av.z;
        As[acol + 3][arow] = av.w;
        *(float4*)&Bs[brow][bcol] = bv;
        __syncthreads();

        #pragma unroll
        for (int kk = 0; kk < 8; kk++) {
            float4 a0 = *(const float4*)&As[kk][tm * 4];
            float4 a1 = *(const float4*)&As[kk][tm * 4 + 64];
            float4 b0 = *(const float4*)&Bs[kk][tn * 4];
            float4 b1 = *(const float4*)&Bs[kk][tn * 4 + 64];
            float ar[8] = {a0.x, a0.y, a0.z, a0.w, a1.x, a1.y, a1.z, a1.w};
            float br[8] = {b0.x, b0.y, b0.z, b0.w, b1.x, b1.y, b1.z, b1.w};
            #pragma unroll
            for (int i = 0; i < 8; i++)
                #pragma unroll
                for (int j = 0; j < 8; j++)
                    acc[i][j] += ar[i] * br[j];
        }
        __syncthreads();
    }

    const int bb = n0 >> 14;           // batch (tile never straddles: 16384 % 128 == 0)
    const int hw = (n0 & 16383) + tn * 4;
    #pragma unroll
    for (int i = 0; i < 8; i++) {
        int r = m0 + tm * 4 + (i & 3) + ((i >= 4) ? 64 : 0);
        float bias = pb[r];
        float* op = out + ((size_t)(bb * CCH + r)) * 16384 + hw;
        float4 v0 = {acc[i][0] + bias, acc[i][1] + bias, acc[i][2] + bias, acc[i][3] + bias};
        float4 v1 = {acc[i][4] + bias, acc[i][5] + bias, acc[i][6] + bias, acc[i][7] + bias};
        *(float4*)op        = v0;
        *(float4*)(op + 64) = v1;
    }
}

// ---------------------------------------------------------------------------
extern "C" void kernel_launch(void* const* d_in, const int* in_sizes, int n_in,
                              void* d_out, int out_size) {
    const float* qkv = (const float*)d_in[0];   // (4, 8, 192, 128, 128) f32
    const float* lsc = (const float*)d_in[1];   // (8,1,1) f32
    const float* rpb = (const float*)d_in[2];   // (225, 8) f32
    const float* pw  = (const float*)d_in[3];   // (512, 512) f32
    const float* pb  = (const float*)d_in[4];   // (512,) f32
    const int*   rel = (const int*)d_in[5];     // (64, 64) i32
    float* out = (float*)d_out;                 // (4, 512, 128, 128) f32

    bias_kernel<<<(NHEAD * AWIN * AWIN + 255) / 256, 256>>>(rpb, rel);
    attn_kernel<<<1024 * NHEAD, 64>>>(qkv, lsc);
    proj_kernel<<<dim3(NPIX / 128, CCH / 128), 256>>>(pw, pb, out);
}

// round 2
// speedup vs baseline: 1.0988x; 1.0988x over previous
#include <cuda_runtime.h>
#include <cstdint>

// Problem constants (fixed shapes from reference)
#define NHEAD 8
#define DH    64
#define AWIN  64        // window area (8x8)
#define HW_   128       // H = W = 128
#define NB    4         // batch
#define NPIX  65536     // B*H*W
#define CCH   512       // channels = NHEAD*DH

typedef unsigned long long u64;

// ---- packed fp32x2 helpers (SASS FFMA2 path, sm_103a) ----------------------
__device__ __forceinline__ u64 pk2(float lo, float hi) {
    u64 d; asm("mov.b64 %0, {%1, %2};" : "=l"(d) : "f"(lo), "f"(hi)); return d;
}
__device__ __forceinline__ void upk2(float& lo, float& hi, u64 v) {
    asm("mov.b64 {%0, %1}, %2;" : "=f"(lo), "=f"(hi) : "l"(v));
}
__device__ __forceinline__ u64 ffma2(u64 a, u64 b, u64 c) {
    u64 d; asm("fma.rn.f32x2 %0, %1, %2, %3;" : "=l"(d) : "l"(a), "l"(b), "l"(c));
    return d;
}

// Scratch: attention output in [c][b*16384 + h*128 + w] layout (GEMM-friendly)
__device__ float g_xbuf[(size_t)CCH * NPIX];
// Precomputed relative position bias: [head][ka][qa]
__device__ float g_bias[NHEAD * AWIN * AWIN];

// ---------------------------------------------------------------------------
// Kernel 0: expand rpb_table via rel_index into [h][ka][qa]
// ---------------------------------------------------------------------------
__global__ void bias_kernel(const float* __restrict__ rpb, const int* __restrict__ rel) {
    int idx = blockIdx.x * blockDim.x + threadIdx.x;
    if (idx >= NHEAD * AWIN * AWIN) return;
    int h  = idx >> 12;          // / 4096
    int r  = idx & 4095;
    int ka = r >> 6;
    int qa = r & 63;
    g_bias[idx] = rpb[rel[qa * AWIN + ka] * NHEAD + h];
}

// ---------------------------------------------------------------------------
// Kernel 1: windowed cosine attention.
// One block = one (window, head). 64 threads, thread t = query row t.
// smem layout [d][a] (d slow, a fast): column reads conflict-free,
// row reads are warp-broadcast. Inner products use packed f32x2 FMA.
// ---------------------------------------------------------------------------
__global__ void __launch_bounds__(64) attn_kernel(const float* __restrict__ qkv,
                                                  const float* __restrict__ lscale) {
    __shared__ float sm[3 * 4096];     // 48 KB: q | k | v, each [64][64]
    float* sq = sm;
    float* sk = sm + 4096;
    float* sv = sm + 8192;

    const int t    = threadIdx.x;      // query index / own k,v column
    const int wh   = blockIdx.x;
    const int head = wh & 7;
    const int win  = wh >> 3;
    const int b    = win >> 8;
    const int wy   = (win >> 4) & 15;
    const int wx   = win & 15;

    // qkv: (B, Hh, 192, 128, 128) row-major
    const float* base = qkv + (size_t)b * (NHEAD * 192 * 16384)
                            + (size_t)head * (192 * 16384)
                            + wy * 8 * HW_ + wx * 8;

    // Cooperative load: iteration d == channel, lane t == window pixel a.
    const int aoff = ((t >> 3) * HW_) + (t & 7);
    #pragma unroll 4
    for (int d = 0; d < 64; d++) {
        int off = d * 16384 + aoff;
        sq[d * 64 + t] = base[off];
        sk[d * 64 + t] = base[off +  64 * 16384];
        sv[d * 64 + t] = base[off + 128 * 16384];
    }
    __syncthreads();

    const float sc = __expf(fminf(lscale[head], 4.6051702f));   // log(100)

    // Normalize own q column (fold in scale) and own k column, in place.
    float q0 = 0.f, q1 = 0.f;
    #pragma unroll 8
    for (int d = 0; d < 64; d += 2) {
        float a = sq[d * 64 + t], bq = sq[(d + 1) * 64 + t];
        q0 += a * a; q1 += bq * bq;
    }
    const float invq = sc / fmaxf(sqrtf(q0 + q1), 1e-12f);
    #pragma unroll 8
    for (int d = 0; d < 64; d++) sq[d * 64 + t] *= invq;

    float k0 = 0.f, k1 = 0.f;
    #pragma unroll 8
    for (int d = 0; d < 64; d += 2) {
        float a = sk[d * 64 + t], bk = sk[(d + 1) * 64 + t];
        k0 += a * a; k1 += bk * bk;
    }
    const float invk = 1.0f / fmaxf(sqrtf(k0 + k1), 1e-12f);
    #pragma unroll 8
    for (int d = 0; d < 64; d++) sk[d * 64 + t] *= invk;
    __syncthreads();   // everyone reads all k columns next

    // Logits: p[ka] = sum_d q[t][d] * k[ka][d]; 32 packed accumulators.
    u64 pacc[32];
    #pragma unroll
    for (int i = 0; i < 32; i++) pacc[i] = 0ull;   // (0.f, 0.f)

    const ulonglong2* sk2 = (const ulonglong2*)sk;
    for (int d = 0; d < 64; d++) {
        float qv = sq[d * 64 + t];                 // own column, conflict-free
        u64 qq = pk2(qv, qv);
        #pragma unroll
        for (int g = 0; g < 16; g++) {
            ulonglong2 kv = sk2[d * 16 + g];       // broadcast LDS.128 = 2 pairs
            pacc[2 * g + 0] = ffma2(qq, kv.x, pacc[2 * g + 0]);
            pacc[2 * g + 1] = ffma2(qq, kv.y, pacc[2 * g + 1]);
        }
    }

    float p[64];
    #pragma unroll
    for (int i = 0; i < 32; i++) upk2(p[2 * i], p[2 * i + 1], pacc[i]);

    // + relative position bias (coalesced global, L2-resident 128KB table)
    const float* gb = g_bias + head * 4096;
    #pragma unroll
    for (int i = 0; i < 64; i++) p[i] += gb[i * 64 + t];

    // Softmax over ka (whole row lives in this thread)
    float m = p[0];
    #pragma unroll
    for (int i = 1; i < 64; i++) m = fmaxf(m, p[i]);
    float s0 = 0.f, s1 = 0.f, s2 = 0.f, s3 = 0.f;
    #pragma unroll
    for (int i = 0; i < 64; i += 4) {
        p[i + 0] = __expf(p[i + 0] - m); s0 += p[i + 0];
        p[i + 1] = __expf(p[i + 1] - m); s1 += p[i + 1];
        p[i + 2] = __expf(p[i + 2] - m); s2 += p[i + 2];
        p[i + 3] = __expf(p[i + 3] - m); s3 += p[i + 3];
    }
    const float inv = 1.0f / ((s0 + s1) + (s2 + s3));

    // Normalize and repack probabilities into pairs for the PV loop.
    u64 pp[32];
    #pragma unroll
    for (int i = 0; i < 32; i++) pp[i] = pk2(p[2 * i] * inv, p[2 * i + 1] * inv);

    // PV: out[t][d] = sum_a p[a] * v[a][d]; store straight to scratch.
    const int pixbase = b * 16384 + (wy * 8 + (t >> 3)) * HW_ + wx * 8 + (t & 7);
    float* xb = g_xbuf + (size_t)(head * DH) * NPIX + pixbase;
    const ulonglong2* sv2 = (const ulonglong2*)sv;
    for (int d = 0; d < 64; d++) {
        u64 a0 = 0ull, a1 = 0ull;
        #pragma unroll
        for (int g = 0; g < 16; g++) {
            ulonglong2 vv = sv2[d * 16 + g];       // broadcast LDS.128 = 2 pairs
            a0 = ffma2(pp[2 * g + 0], vv.x, a0);
            a1 = ffma2(pp[2 * g + 1], vv.y, a1);
        }
        float x0, x1, x2, x3;
        upk2(x0, x1, a0);
        upk2(x2, x3, a1);
        xb[(size_t)d * NPIX] = (x0 + x1) + (x2 + x3);
    }
}

// ---------------------------------------------------------------------------
// Kernel 2: projection GEMM.  out[M=512][N=65536] = W[512][512] @ X[512][65536] + b
// 128x128x8 SGEMM, 256 threads, 8x8 per thread, inner product via FFMA2.
// ---------------------------------------------------------------------------
__global__ void __launch_bounds__(256) proj_kernel(const float* __restrict__ W,
                                                   const float* __restrict__ pb,
                                                   float* __restrict__ out) {
    __shared__ float As[8][128];   // A transposed: As[k][m]
    __shared__ float Bs[8][128];

    const int tid = threadIdx.x;
    const int m0  = blockIdx.y * 128;
    const int n0  = blockIdx.x * 128;
    const int tm  = tid >> 4;       // 0..15
    const int tn  = tid & 15;       // 0..15

    u64 acc[8][4];                  // [i][j-pair]: 8x8 fp32 as 8x4 f32x2
    #pragma unroll
    for (int i = 0; i < 8; i++)
        #pragma unroll
        for (int j = 0; j < 4; j++) acc[i][j] = 0ull;

    const int arow = tid >> 1;             // 0..127
    const int acol = (tid & 1) * 4;        // 0 or 4
    const int brow = tid >> 5;             // 0..7
    const int bcol = (tid & 31) * 4;

    const float* Ap = W + (m0 + arow) * CCH + acol;
    const float* Bp = g_xbuf + (size_t)brow * NPIX + n0 + bcol;

    for (int kk0 = 0; kk0 < CCH; kk0 += 8) {
        float4 av = *(const float4*)(Ap + kk0);
        float4 bv = *(const float4*)(Bp + (size_t)kk0 * NPIX);
        As[acol + 0][arow] = av.x;
        As[acol + 1][arow] = av.y;
        As[acol + 2][arow] = av.z;
        As[acol + 3][arow] = av.w;
        *(float4*)&Bs[brow][bcol] = bv;
        __syncthreads();

        #pragma unroll
        for (int kk = 0; kk < 8; kk++) {
            float4 a0 = *(const float4*)&As[kk][tm * 4];
            float4 a1 = *(const float4*)&As[kk][tm * 4 + 64];
            ulonglong2 bq0 = *(const ulonglong2*)&Bs[kk][tn * 4];        // 2 pairs
            ulonglong2 bq1 = *(const ulonglong2*)&Bs[kk][tn * 4 + 64];   // 2 pairs
            u64 bp4[4] = {bq0.x, bq0.y, bq1.x, bq1.y};
            float ar[8] = {a0.x, a0.y, a0.z, a0.w, a1.x, a1.y, a1.z, a1.w};
            #pragma unroll
            for (int i = 0; i < 8; i++) {
                u64 aa = pk2(ar[i], ar[i]);
                #pragma unroll
                for (int j = 0; j < 4; j++)
                    acc[i][j] = ffma2(aa, bp4[j], acc[i][j]);
            }
        }
        __syncthreads();
    }

    const int bb = n0 >> 14;           // batch (tile never straddles: 16384 % 128 == 0)
    const int hw = (n0 & 16383) + tn * 4;
    #pragma unroll
    for (int i = 0; i < 8; i++) {
        int r = m0 + tm * 4 + (i & 3) + ((i >= 4) ? 64 : 0);
        float bias = pb[r];
        float c0, c1, c2, c3, c4, c5, c6, c7;
        upk2(c0, c1, acc[i][0]);
        upk2(c2, c3, acc[i][1]);
        upk2(c4, c5, acc[i][2]);
        upk2(c6, c7, acc[i][3]);
        float* op = out + ((size_t)(bb * CCH + r)) * 16384 + hw;
        float4 v0 = {c0 + bias, c1 + bias, c2 + bias, c3 + bias};
        float4 v1 = {c4 + bias, c5 + bias, c6 + bias, c7 + bias};
        *(float4*)op        = v0;
        *(float4*)(op + 64) = v1;
    }
}

// ---------------------------------------------------------------------------
extern "C" void kernel_launch(void* const* d_in, const int* in_sizes, int n_in,
                              void* d_out, int out_size) {
    const float* qkv = (const float*)d_in[0];   // (4, 8, 192, 128, 128) f32
    const float* lsc = (const float*)d_in[1];   // (8,1,1) f32
    const float* rpb = (const float*)d_in[2];   // (225, 8) f32
    const float* pw  = (const float*)d_in[3];   // (512, 512) f32
    const float* pb  = (const float*)d_in[4];   // (512,) f32
    const int*   rel = (const int*)d_in[5];     // (64, 64) i32
    float* out = (float*)d_out;                 // (4, 512, 128, 128) f32

    bias_kernel<<<(NHEAD * AWIN * AWIN + 255) / 256, 256>>>(rpb, rel);
    attn_kernel<<<1024 * NHEAD, 64>>>(qkv, lsc);
    proj_kernel<<<dim3(NPIX / 128, CCH / 128), 256>>>(pw, pb, out);
}

// round 4
// speedup vs baseline: 1.4498x; 1.3195x over previous
#include <cuda_runtime.h>
#include <cuda_bf16.h>
#include <cstdint>

// Problem constants (fixed shapes)
#define NHEAD 8
#define DH    64
#define HW_   128
#define NPIX  65536      // B*H*W
#define CCH   512        // channels

typedef unsigned long long u64;
typedef unsigned int u32;

// ---- packed fp32x2 helpers -------------------------------------------------
__device__ __forceinline__ u64 pk2(float lo, float hi) {
    u64 d; asm("mov.b64 %0, {%1, %2};" : "=l"(d) : "f"(lo), "f"(hi)); return d;
}
__device__ __forceinline__ void upk2(float& lo, float& hi, u64 v) {
    asm("mov.b64 {%0, %1}, %2;" : "=f"(lo), "=f"(hi) : "l"(v));
}
__device__ __forceinline__ u64 ffma2(u64 a, u64 b, u64 c) {
    u64 d; asm("fma.rn.f32x2 %0, %1, %2, %3;" : "=l"(d) : "l"(a), "l"(b), "l"(c));
    return d;
}

// ---- scratch (allocation-free rule: __device__ globals) --------------------
__device__ __nv_bfloat16 g_xh[(size_t)NPIX * CCH];   // X hi, [pixel][channel]
__device__ __nv_bfloat16 g_xl[(size_t)NPIX * CCH];   // X lo
__device__ __nv_bfloat16 g_wh[CCH * CCH];            // W hi, row-major [m][k]
__device__ __nv_bfloat16 g_wl[CCH * CCH];            // W lo

// ---- family-portable PTX helpers ------------------------------------------
__device__ __forceinline__ u32 smem_u32(const void* p) {
    u32 a; asm("{ .reg .u64 t; cvta.to.shared.u64 t, %1; cvt.u32.u64 %0, t; }"
               : "=r"(a) : "l"(p));
    return a;
}
__device__ __forceinline__ void cpa16(u32 dst, const void* src) {
    asm volatile("cp.async.cg.shared.global [%0], [%1], 16;" :: "r"(dst), "l"(src));
}
#define CPA_COMMIT() asm volatile("cp.async.commit_group;" ::: "memory")
#define CPA_WAIT(n)  asm volatile("cp.async.wait_group %0;" :: "n"(n) : "memory")

__device__ __forceinline__ void ldmx4(u32* r, u32 addr) {
    asm volatile("ldmatrix.sync.aligned.m8n8.x4.shared.b16 {%0,%1,%2,%3}, [%4];"
        : "=r"(r[0]), "=r"(r[1]), "=r"(r[2]), "=r"(r[3]) : "r"(addr));
}
__device__ __forceinline__ void ldmx2(u32* r, u32 addr) {
    asm volatile("ldmatrix.sync.aligned.m8n8.x2.shared.b16 {%0,%1}, [%2];"
        : "=r"(r[0]), "=r"(r[1]) : "r"(addr));
}
__device__ __forceinline__ void mma16816(float* c, const u32* a, const u32* b) {
    asm volatile("mma.sync.aligned.m16n8k16.row.col.f32.bf16.bf16.f32 "
        "{%0,%1,%2,%3}, {%4,%5,%6,%7}, {%8,%9}, {%0,%1,%2,%3};"
        : "+f"(c[0]), "+f"(c[1]), "+f"(c[2]), "+f"(c[3])
        : "r"(a[0]), "r"(a[1]), "r"(a[2]), "r"(a[3]), "r"(b[0]), "r"(b[1]));
}

// ---------------------------------------------------------------------------
// Kernel: split W (fp32) -> bf16 hi/lo
// ---------------------------------------------------------------------------
__global__ void __launch_bounds__(256) wsplit_kernel(const float* __restrict__ W) {
    int i = blockIdx.x * 256 + threadIdx.x;       // 262144 total
    float x = W[i];
    __nv_bfloat16 h = __float2bfloat16(x);
    g_wh[i] = h;
    g_wl[i] = __float2bfloat16(x - __bfloat162float(h));
}

// ---------------------------------------------------------------------------
// Kernel: windowed cosine attention. One block = (window, head), 64 threads.
// Emits X as bf16 hi/lo pairs in [pixel][channel] layout.
// ---------------------------------------------------------------------------
__global__ void __launch_bounds__(64) attn_kernel(const float* __restrict__ qkv,
                                                  const float* __restrict__ lscale,
                                                  const float* __restrict__ rpb,
                                                  const int* __restrict__ rel) {
    __shared__ float sm[3 * 4096];     // q | k | v, each [d][a] 64x64
    float* sq = sm;
    float* sk = sm + 4096;
    float* sv = sm + 8192;

    const int t    = threadIdx.x;
    const int wh   = blockIdx.x;
    const int head = wh & 7;
    const int win  = wh >> 3;
    const int b    = win >> 8;
    const int wy   = (win >> 4) & 15;
    const int wx   = win & 15;

    const float* base = qkv + (size_t)b * (NHEAD * 192 * 16384)
                            + (size_t)head * (192 * 16384)
                            + wy * 8 * HW_ + wx * 8;

    const int aoff = ((t >> 3) * HW_) + (t & 7);
    #pragma unroll 4
    for (int d = 0; d < 64; d++) {
        int off = d * 16384 + aoff;
        sq[d * 64 + t] = base[off];
        sk[d * 64 + t] = base[off +  64 * 16384];
        sv[d * 64 + t] = base[off + 128 * 16384];
    }
    __syncthreads();

    const float sc = __expf(fminf(lscale[head], 4.6051702f));

    float q0 = 0.f, q1 = 0.f;
    #pragma unroll 8
    for (int d = 0; d < 64; d += 2) {
        float a = sq[d * 64 + t], bq = sq[(d + 1) * 64 + t];
        q0 += a * a; q1 += bq * bq;
    }
    const float invq = sc / fmaxf(sqrtf(q0 + q1), 1e-12f);
    #pragma unroll 8
    for (int d = 0; d < 64; d++) sq[d * 64 + t] *= invq;

    float k0 = 0.f, k1 = 0.f;
    #pragma unroll 8
    for (int d = 0; d < 64; d += 2) {
        float a = sk[d * 64 + t], bk = sk[(d + 1) * 64 + t];
        k0 += a * a; k1 += bk * bk;
    }
    const float invk = 1.0f / fmaxf(sqrtf(k0 + k1), 1e-12f);
    #pragma unroll 8
    for (int d = 0; d < 64; d++) sk[d * 64 + t] *= invk;
    __syncthreads();

    // Logits via packed FMA
    u64 pacc[32];
    #pragma unroll
    for (int i = 0; i < 32; i++) pacc[i] = 0ull;

    const ulonglong2* sk2 = (const ulonglong2*)sk;
    for (int d = 0; d < 64; d++) {
        float qv = sq[d * 64 + t];
        u64 qq = pk2(qv, qv);
        #pragma unroll
        for (int g = 0; g < 16; g++) {
            ulonglong2 kv = sk2[d * 16 + g];
            pacc[2 * g + 0] = ffma2(qq, kv.x, pacc[2 * g + 0]);
            pacc[2 * g + 1] = ffma2(qq, kv.y, pacc[2 * g + 1]);
        }
    }

    float p[64];
    #pragma unroll
    for (int i = 0; i < 32; i++) upk2(p[2 * i], p[2 * i + 1], pacc[i]);

    // + relative position bias, gathered inline (tables are L1/L2-resident)
    const int* relrow = rel + t * 64;
    #pragma unroll
    for (int i = 0; i < 64; i++) p[i] += rpb[relrow[i] * NHEAD + head];

    // Softmax
    float m = p[0];
    #pragma unroll
    for (int i = 1; i < 64; i++) m = fmaxf(m, p[i]);
    float s0 = 0.f, s1 = 0.f, s2 = 0.f, s3 = 0.f;
    #pragma unroll
    for (int i = 0; i < 64; i += 4) {
        p[i + 0] = __expf(p[i + 0] - m); s0 += p[i + 0];
        p[i + 1] = __expf(p[i + 1] - m); s1 += p[i + 1];
        p[i + 2] = __expf(p[i + 2] - m); s2 += p[i + 2];
        p[i + 3] = __expf(p[i + 3] - m); s3 += p[i + 3];
    }
    const float inv = 1.0f / ((s0 + s1) + (s2 + s3));
    #pragma unroll
    for (int i = 0; i < 32; i++) pacc[i] = pk2(p[2 * i], p[2 * i + 1]);

    // PV + bf16 hi/lo split store, [pixel][channel]
    const int pix = b * 16384 + (wy * 8 + (t >> 3)) * HW_ + wx * 8 + (t & 7);
    const size_t xoff = (size_t)pix * CCH + head * DH;
    uint4* xh4 = (uint4*)(g_xh + xoff);
    uint4* xl4 = (uint4*)(g_xl + xoff);
    const ulonglong2* sv2 = (const ulonglong2*)sv;

    #pragma unroll
    for (int dg = 0; dg < 8; dg++) {
        u32 hw_[4], lw_[4];
        #pragma unroll
        for (int dd = 0; dd < 8; dd += 2) {
            float vpair[2];
            #pragma unroll
            for (int u = 0; u < 2; u++) {
                int d = dg * 8 + dd + u;
                u64 a0 = 0ull, a1 = 0ull;
                #pragma unroll
                for (int g = 0; g < 16; g++) {
                    ulonglong2 vv = sv2[d * 16 + g];
                    a0 = ffma2(pacc[2 * g + 0], vv.x, a0);
                    a1 = ffma2(pacc[2 * g + 1], vv.y, a1);
                }
                float x0, x1, x2, x3;
                upk2(x0, x1, a0);
                upk2(x2, x3, a1);
                vpair[u] = ((x0 + x1) + (x2 + x3)) * inv;
            }
            __nv_bfloat16 h0 = __float2bfloat16(vpair[0]);
            __nv_bfloat16 h1 = __float2bfloat16(vpair[1]);
            __nv_bfloat16 l0 = __float2bfloat16(vpair[0] - __bfloat162float(h0));
            __nv_bfloat16 l1 = __float2bfloat16(vpair[1] - __bfloat162float(h1));
            hw_[dd >> 1] = (u32)__bfloat16_as_ushort(h0) | ((u32)__bfloat16_as_ushort(h1) << 16);
            lw_[dd >> 1] = (u32)__bfloat16_as_ushort(l0) | ((u32)__bfloat16_as_ushort(l1) << 16);
        }
        xh4[dg] = make_uint4(hw_[0], hw_[1], hw_[2], hw_[3]);
        xl4[dg] = make_uint4(lw_[0], lw_[1], lw_[2], lw_[3]);
    }
}

// ---------------------------------------------------------------------------
// Kernel: projection GEMM via mma.sync bf16 (3-split, fp32 accum).
// CTA: 128 channels (M) x 128 pixels (N), K=512 in 16 chunks of 32.
// 8 warps = 2(M) x 4(N); warp tile 64x32; double-buffered cp.async.
// ---------------------------------------------------------------------------
#define BK   32
#define LDT  40            // BK + 8 pad (bf16 units): stride 80B, ldmatrix conflict-free
#define TILE_E (128 * LDT) // 5120 bf16 per tile
#define STG_E  (4 * TILE_E)
#define PROJ_SMEM (2 * STG_E * 2)   // 81920 bytes

__device__ __forceinline__ void proj_load_stage(u32 sbase, int m0g, int n0g, int k0, int tid) {
    // tiles within stage: Wh | Wl | Xh | Xl, each [128][LDT]
    #pragma unroll
    for (int j = 0; j < 2; j++) {
        int id = tid + j * 256;          // 0..511
        int r  = id >> 2;                // row 0..127
        int c  = (id & 3) * 8;           // col in bf16 (8 = 16B)
        u32 dst = sbase + 2 * (r * LDT + c);
        size_t gw = (size_t)(m0g + r) * CCH + k0 + c;
        size_t gx = (size_t)(n0g + r) * CCH + k0 + c;
        cpa16(dst,                  g_wh + gw);
        cpa16(dst + 2 * TILE_E,     g_wl + gw);
        cpa16(dst + 2 * 2 * TILE_E, g_xh + gx);
        cpa16(dst + 2 * 3 * TILE_E, g_xl + gx);
    }
    CPA_COMMIT();
}

__global__ void __launch_bounds__(256) proj_hmma_kernel(const float* __restrict__ pb,
                                                        float* __restrict__ out) {
    extern __shared__ __nv_bfloat16 psm[];
    const int tid  = threadIdx.x;
    const int wid  = tid >> 5;
    const int lane = tid & 31;
    const int wm   = wid >> 2;          // 0..1
    const int wn   = wid & 3;           // 0..3

    const int m0g = blockIdx.x * 128;   // channel tile (fast dim: share X in L2)
    const int n0g = blockIdx.y * 128;   // pixel tile

    const u32 sb = smem_u32(psm);

    float acc[4][4][4];
    #pragma unroll
    for (int i = 0; i < 4; i++)
        #pragma unroll
        for (int j = 0; j < 4; j++)
            #pragma unroll
            for (int r = 0; r < 4; r++) acc[i][j][r] = 0.f;

    proj_load_stage(sb,             m0g, n0g, 0,  tid);
    proj_load_stage(sb + 2 * STG_E, m0g, n0g, 32, tid);

    // ldmatrix address components (fixed per thread)
    const int arow = wm * 64 + (lane & 15);
    const int acol = (lane >> 4) * 8;
    const int brow = wn * 32 + (lane & 7);
    const int bcol = ((lane >> 3) & 1) * 8;

    #pragma unroll 1
    for (int kc = 0; kc < 16; kc++) {
        const int s = kc & 1;
        const u32 stg = sb + s * 2 * STG_E;
        if (kc < 15) { CPA_WAIT(1); } else { CPA_WAIT(0); }
        __syncthreads();

        const u32 whb = stg;
        const u32 wlb = stg + 2 * TILE_E;
        const u32 xhb = stg + 2 * 2 * TILE_E;
        const u32 xlb = stg + 2 * 3 * TILE_E;

        #pragma unroll
        for (int ks = 0; ks < 2; ks++) {
            const int kf = ks * 16;
            u32 ah[4][4], al[4][4], bh[4][2], bl[4][2];
            #pragma unroll
            for (int i = 0; i < 4; i++) {
                u32 ao = 2 * ((arow + i * 16) * LDT + acol + kf);
                ldmx4(ah[i], whb + ao);
                ldmx4(al[i], wlb + ao);
            }
            #pragma unroll
            for (int j = 0; j < 4; j++) {
                u32 bo = 2 * ((brow + j * 8) * LDT + bcol + kf);
                ldmx2(bh[j], xhb + bo);
                ldmx2(bl[j], xlb + bo);
            }
            #pragma unroll
            for (int i = 0; i < 4; i++)
                #pragma unroll
                for (int j = 0; j < 4; j++) {
                    mma16816(acc[i][j], ah[i], bh[j]);
                    mma16816(acc[i][j], ah[i], bl[j]);
                    mma16816(acc[i][j], al[i], bh[j]);
                }
        }
        __syncthreads();
        if (kc + 2 < 16) proj_load_stage(stg, m0g, n0g, (kc + 2) * 32, tid);
    }

    // Epilogue: thread holds D[m..][n pair]; coalesced float2 stores (pixel dim)
    const int bb = n0g >> 14;
    const int hwb = (n0g & 16383) + wn * 32 + 2 * (lane & 3);
    #pragma unroll
    for (int i = 0; i < 4; i++) {
        int m = m0g + wm * 64 + i * 16 + (lane >> 2);
        float bias0 = pb[m];
        float bias8 = pb[m + 8];
        float* r0 = out + ((size_t)(bb * CCH + m)) * 16384 + hwb;
        float* r8 = out + ((size_t)(bb * CCH + m + 8)) * 16384 + hwb;
        #pragma unroll
        for (int j = 0; j < 4; j++) {
            float2 v0 = {acc[i][j][0] + bias0, acc[i][j][1] + bias0};
            float2 v1 = {acc[i][j][2] + bias8, acc[i][j][3] + bias8};
            *(float2*)(r0 + j * 8) = v0;
            *(float2*)(r8 + j * 8) = v1;
        }
    }
}

// ---------------------------------------------------------------------------
extern "C" void kernel_launch(void* const* d_in, const int* in_sizes, int n_in,
                              void* d_out, int out_size) {
    const float* qkv = (const float*)d_in[0];   // (4, 8, 192, 128, 128) f32
    const float* lsc = (const float*)d_in[1];   // (8,1,1) f32
    const float* rpb = (const float*)d_in[2];   // (225, 8) f32
    const float* pw  = (const float*)d_in[3];   // (512, 512) f32
    const float* pb  = (const float*)d_in[4];   // (512,) f32
    const int*   rel = (const int*)d_in[5];     // (64, 64) i32
    float* out = (float*)d_out;                 // (4, 512, 128, 128) f32

    cudaFuncSetAttribute(proj_hmma_kernel,
                         cudaFuncAttributeMaxDynamicSharedMemorySize, PROJ_SMEM);

    wsplit_kernel<<<CCH * CCH / 256, 256>>>(pw);
    attn_kernel<<<1024 * NHEAD, 64>>>(qkv, lsc, rpb, rel);
    proj_hmma_kernel<<<dim3(CCH / 128, NPIX / 128), 256, PROJ_SMEM>>>(pb, out);
}

// round 5
// speedup vs baseline: 1.7828x; 1.2297x over previous
#include <cuda_runtime.h>
#include <cuda_bf16.h>
#include <cstdint>

// Problem constants (fixed shapes)
#define NHEAD 8
#define DH    64
#define HW_   128
#define NPIX  65536      // B*H*W
#define CCH   512        // channels

typedef unsigned long long u64;
typedef unsigned int u32;

// ---- scratch (allocation-free rule: __device__ globals) --------------------
__device__ __nv_bfloat16 g_xh[(size_t)NPIX * CCH];   // X hi, [pixel][channel]
__device__ __nv_bfloat16 g_xl[(size_t)NPIX * CCH];   // X lo
__device__ __nv_bfloat16 g_wh[CCH * CCH];            // W hi, row-major [m][k]
__device__ __nv_bfloat16 g_wl[CCH * CCH];            // W lo
__device__ float g_bias[NHEAD * 64 * 64];            // [head][q][k]

// ---- family-portable PTX helpers ------------------------------------------
__device__ __forceinline__ u32 smem_u32(const void* p) {
    u32 a; asm("{ .reg .u64 t; cvta.to.shared.u64 t, %1; cvt.u32.u64 %0, t; }"
               : "=r"(a) : "l"(p));
    return a;
}
__device__ __forceinline__ void cpa16(u32 dst, const void* src) {
    asm volatile("cp.async.cg.shared.global [%0], [%1], 16;" :: "r"(dst), "l"(src));
}
#define CPA_COMMIT() asm volatile("cp.async.commit_group;" ::: "memory")
#define CPA_WAIT(n)  asm volatile("cp.async.wait_group %0;" :: "n"(n) : "memory")

__device__ __forceinline__ void ldmx4(u32* r, u32 addr) {
    asm volatile("ldmatrix.sync.aligned.m8n8.x4.shared.b16 {%0,%1,%2,%3}, [%4];"
        : "=r"(r[0]), "=r"(r[1]), "=r"(r[2]), "=r"(r[3]) : "r"(addr));
}
__device__ __forceinline__ void ldmx2(u32* r, u32 addr) {
    asm volatile("ldmatrix.sync.aligned.m8n8.x2.shared.b16 {%0,%1}, [%2];"
        : "=r"(r[0]), "=r"(r[1]) : "r"(addr));
}
__device__ __forceinline__ void mma16816(float* c, const u32* a, const u32* b) {
    asm volatile("mma.sync.aligned.m16n8k16.row.col.f32.bf16.bf16.f32 "
        "{%0,%1,%2,%3}, {%4,%5,%6,%7}, {%8,%9}, {%0,%1,%2,%3};"
        : "+f"(c[0]), "+f"(c[1]), "+f"(c[2]), "+f"(c[3])
        : "r"(a[0]), "r"(a[1]), "r"(a[2]), "r"(a[3]), "r"(b[0]), "r"(b[1]));
}
// pack two fp32 -> bf16 pair (hi/lo split), packed for mma b16x2 registers
__device__ __forceinline__ void bfsplit2(float x0, float x1, u32& h, u32& l) {
    __nv_bfloat16 h0 = __float2bfloat16(x0);
    __nv_bfloat16 h1 = __float2bfloat16(x1);
    __nv_bfloat16 l0 = __float2bfloat16(x0 - __bfloat162float(h0));
    __nv_bfloat16 l1 = __float2bfloat16(x1 - __bfloat162float(h1));
    h = (u32)__bfloat16_as_ushort(h0) | ((u32)__bfloat16_as_ushort(h1) << 16);
    l = (u32)__bfloat16_as_ushort(l0) | ((u32)__bfloat16_as_ushort(l1) << 16);
}

// ---------------------------------------------------------------------------
// Kernel: expand rpb_table via rel_index into [head][q][k]
// ---------------------------------------------------------------------------
__global__ void bias_kernel(const float* __restrict__ rpb, const int* __restrict__ rel) {
    int idx = blockIdx.x * blockDim.x + threadIdx.x;   // 32768
    if (idx >= NHEAD * 64 * 64) return;
    int h = idx >> 12;
    int r = idx & 4095;                                // q*64 + k
    g_bias[idx] = rpb[rel[r] * NHEAD + h];
}

// ---------------------------------------------------------------------------
// Kernel: split W (fp32) -> bf16 hi/lo
// ---------------------------------------------------------------------------
__global__ void __launch_bounds__(256) wsplit_kernel(const float* __restrict__ W) {
    int i = blockIdx.x * 256 + threadIdx.x;
    float x = W[i];
    __nv_bfloat16 h = __float2bfloat16(x);
    g_wh[i] = h;
    g_wl[i] = __float2bfloat16(x - __bfloat162float(h));
}

// ---------------------------------------------------------------------------
// Kernel: windowed cosine attention on mma.sync bf16 (hi/lo 4-term splits).
// Block = one (window, head), 128 threads / 4 warps; warp w = query rows 16w..
// ---------------------------------------------------------------------------
#define PADF 65
#define PADB 68
#define PADH 72
// smem byte offsets
#define SQF_O 0
#define SKF_O 16640
#define QH_O  33280
#define QL_O  42496
#define KH_O  51712
#define KL_O  60928
#define VH_O  70144
#define VL_O  79360
#define SB_O  88576
#define ATTN_SMEM 105984

__global__ void __launch_bounds__(128) attn_kernel(const float* __restrict__ qkv,
                                                   const float* __restrict__ lscale) {
    extern __shared__ char smem[];
    float* sqf = (float*)(smem + SQF_O);
    float* skf = (float*)(smem + SKF_O);
    __nv_bfloat16* qhp = (__nv_bfloat16*)(smem + QH_O);
    __nv_bfloat16* qlp = (__nv_bfloat16*)(smem + QL_O);
    __nv_bfloat16* khp = (__nv_bfloat16*)(smem + KH_O);
    __nv_bfloat16* klp = (__nv_bfloat16*)(smem + KL_O);
    __nv_bfloat16* vhp = (__nv_bfloat16*)(smem + VH_O);
    __nv_bfloat16* vlp = (__nv_bfloat16*)(smem + VL_O);
    float* sbias = (float*)(smem + SB_O);

    const int tid  = threadIdx.x;
    const int lane = tid & 31;
    const int wrp  = tid >> 5;

    const int wh   = blockIdx.x;
    const int head = wh & 7;
    const int win  = wh >> 3;
    const int b    = win >> 8;
    const int wy   = (win >> 4) & 15;
    const int wx   = win & 15;

    const float* base = qkv + (size_t)b * (NHEAD * 192 * 16384)
                            + (size_t)head * (192 * 16384)
                            + wy * 8 * HW_ + wx * 8;

    // ---- load: q,k staged fp32 [a][d]; v split directly to bf16 [d][a] ----
    {
        const int a = tid & 63;
        const int aoff = (a >> 3) * HW_ + (a & 7);
        const int d0 = (tid >> 6) * 32;
        #pragma unroll 4
        for (int i = 0; i < 32; i++) {
            int d = d0 + i;
            int off = d * 16384 + aoff;
            sqf[a * PADF + d] = base[off];
            skf[a * PADF + d] = base[off + 64 * 16384];
            float xv = base[off + 128 * 16384];
            __nv_bfloat16 h = __float2bfloat16(xv);
            vhp[d * PADH + a] = h;
            vlp[d * PADH + a] = __float2bfloat16(xv - __bfloat162float(h));
        }
        // bias tile for this head -> smem [q][PADB]
        const float4* gb4 = (const float4*)(g_bias + head * 4096);
        #pragma unroll
        for (int i = tid; i < 1024; i += 128) {
            float4 v4 = gb4[i];
            int q = i >> 4, k4 = (i & 15) * 4;
            *(float4*)&sbias[q * PADB + k4] = v4;
        }
    }
    __syncthreads();

    // ---- normalize (thread t<64: q row t; t>=64: k row t-64), emit bf16 splits
    {
        const float sc = __expf(fminf(lscale[head], 4.6051702f));
        const int r = tid & 63;
        const float* row = ((tid < 64) ? sqf : skf) + r * PADF;
        float ss = 0.f;
        #pragma unroll 16
        for (int d = 0; d < 64; d++) { float x = row[d]; ss += x * x; }
        const float innv = ((tid < 64) ? sc : 1.0f) / fmaxf(sqrtf(ss), 1e-12f);
        __nv_bfloat16* dh = ((tid < 64) ? qhp : khp) + r * PADH;
        __nv_bfloat16* dl = ((tid < 64) ? qlp : klp) + r * PADH;
        #pragma unroll 16
        for (int d = 0; d < 64; d++) {
            float x = row[d] * innv;
            __nv_bfloat16 h = __float2bfloat16(x);
            dh[d] = h;
            dl[d] = __float2bfloat16(x - __bfloat162float(h));
        }
    }
    __syncthreads();

    const u32 sb = smem_u32(smem);
    const u32 qh_s = sb + QH_O, ql_s = sb + QL_O;
    const u32 kh_s = sb + KH_O, kl_s = sb + KL_O;
    const u32 vh_s = sb + VH_O, vl_s = sb + VL_O;

    const int m0 = wrp * 16;
    const int arow = m0 + (lane & 15);
    const int acol = (lane >> 4) * 8;
    const int brl  = lane & 7;
    const int bcl  = ((lane >> 3) & 1) * 8;

    // ---- S = (Qh+Ql)(Kh+Kl)^T : acc[j][4], j = key n-tile (8 wide) ----
    float acc[8][4];
    #pragma unroll
    for (int j = 0; j < 8; j++)
        #pragma unroll
        for (int r = 0; r < 4; r++) acc[j][r] = 0.f;

    #pragma unroll
    for (int ks = 0; ks < 4; ks++) {
        const int kf = ks * 16;
        u32 aqh[4], aql[4];
        u32 ao = 2 * (arow * PADH + acol + kf);
        ldmx4(aqh, qh_s + ao);
        ldmx4(aql, ql_s + ao);
        #pragma unroll
        for (int j = 0; j < 8; j++) {
            u32 bkh[2], bkl[2];
            u32 bo = 2 * ((j * 8 + brl) * PADH + bcl + kf);
            ldmx2(bkh, kh_s + bo);
            ldmx2(bkl, kl_s + bo);
            mma16816(acc[j], aqh, bkh);
            mma16816(acc[j], aqh, bkl);
            mma16816(acc[j], aql, bkh);
            mma16816(acc[j], aql, bkl);
        }
    }

    // ---- bias + softmax on fragments ----
    const int r0 = m0 + (lane >> 2);
    const int cb = 2 * (lane & 3);
    #pragma unroll
    for (int j = 0; j < 8; j++) {
        int c = 8 * j + cb;
        acc[j][0] += sbias[r0 * PADB + c];
        acc[j][1] += sbias[r0 * PADB + c + 1];
        acc[j][2] += sbias[(r0 + 8) * PADB + c];
        acc[j][3] += sbias[(r0 + 8) * PADB + c + 1];
    }
    float mx0 = -1e30f, mx1 = -1e30f;
    #pragma unroll
    for (int j = 0; j < 8; j++) {
        mx0 = fmaxf(mx0, fmaxf(acc[j][0], acc[j][1]));
        mx1 = fmaxf(mx1, fmaxf(acc[j][2], acc[j][3]));
    }
    mx0 = fmaxf(mx0, __shfl_xor_sync(0xffffffffu, mx0, 1));
    mx0 = fmaxf(mx0, __shfl_xor_sync(0xffffffffu, mx0, 2));
    mx1 = fmaxf(mx1, __shfl_xor_sync(0xffffffffu, mx1, 1));
    mx1 = fmaxf(mx1, __shfl_xor_sync(0xffffffffu, mx1, 2));
    float s0 = 0.f, s1 = 0.f;
    #pragma unroll
    for (int j = 0; j < 8; j++) {
        acc[j][0] = __expf(acc[j][0] - mx0); s0 += acc[j][0];
        acc[j][1] = __expf(acc[j][1] - mx0); s0 += acc[j][1];
        acc[j][2] = __expf(acc[j][2] - mx1); s1 += acc[j][2];
        acc[j][3] = __expf(acc[j][3] - mx1); s1 += acc[j][3];
    }
    s0 += __shfl_xor_sync(0xffffffffu, s0, 1);
    s0 += __shfl_xor_sync(0xffffffffu, s0, 2);
    s1 += __shfl_xor_sync(0xffffffffu, s1, 1);
    s1 += __shfl_xor_sync(0xffffffffu, s1, 2);
    const float inv0 = 1.0f / s0, inv1 = 1.0f / s1;
    #pragma unroll
    for (int j = 0; j < 8; j++) {
        acc[j][0] *= inv0; acc[j][1] *= inv0;
        acc[j][2] *= inv1; acc[j][3] *= inv1;
    }

    // ---- repack P C-fragments as A-fragments (in-register, FA2 identity) ----
    u32 aph[4][4], apl[4][4];
    #pragma unroll
    for (int kk = 0; kk < 4; kk++) {
        bfsplit2(acc[2 * kk][0],     acc[2 * kk][1],     aph[kk][0], apl[kk][0]);
        bfsplit2(acc[2 * kk][2],     acc[2 * kk][3],     aph[kk][1], apl[kk][1]);
        bfsplit2(acc[2 * kk + 1][0], acc[2 * kk + 1][1], aph[kk][2], apl[kk][2]);
        bfsplit2(acc[2 * kk + 1][2], acc[2 * kk + 1][3], aph[kk][3], apl[kk][3]);
    }

    // ---- O = (Ph+Pl)(Vh+Vl), V as B = [d][a] ----
    float o[8][4];
    #pragma unroll
    for (int j = 0; j < 8; j++)
        #pragma unroll
        for (int r = 0; r < 4; r++) o[j][r] = 0.f;

    #pragma unroll
    for (int ks = 0; ks < 4; ks++) {
        const int kf = ks * 16;
        #pragma unroll
        for (int jd = 0; jd < 8; jd++) {
            u32 bvh[2], bvl[2];
            u32 bo = 2 * ((jd * 8 + brl) * PADH + bcl + kf);
            ldmx2(bvh, vh_s + bo);
            ldmx2(bvl, vl_s + bo);
            mma16816(o[jd], aph[ks], bvh);
            mma16816(o[jd], aph[ks], bvl);
            mma16816(o[jd], apl[ks], bvh);
            mma16816(o[jd], apl[ks], bvl);
        }
    }

    // ---- store O as bf16 hi/lo to X [pixel][channel] ----
    const int pr0 = b * 16384 + (wy * 8 + (r0 >> 3)) * HW_ + wx * 8 + (r0 & 7);
    const int r1 = r0 + 8;
    const int pr1 = b * 16384 + (wy * 8 + (r1 >> 3)) * HW_ + wx * 8 + (r1 & 7);
    const size_t x0 = (size_t)pr0 * CCH + head * 64;
    const size_t x1 = (size_t)pr1 * CCH + head * 64;
    #pragma unroll
    for (int j = 0; j < 8; j++) {
        int c = 8 * j + cb;
        u32 h0, l0, h1, l1;
        bfsplit2(o[j][0], o[j][1], h0, l0);
        bfsplit2(o[j][2], o[j][3], h1, l1);
        *(u32*)(g_xh + x0 + c) = h0;
        *(u32*)(g_xl + x0 + c) = l0;
        *(u32*)(g_xh + x1 + c) = h1;
        *(u32*)(g_xl + x1 + c) = l1;
    }
}

// ---------------------------------------------------------------------------
// Kernel: projection GEMM via mma.sync bf16 (3-split, fp32 accum).
// CTA: 128 channels (M) x 128 pixels (N), K=512 in 16 chunks of 32.
// ---------------------------------------------------------------------------
#define BK   32
#define LDT  40
#define TILE_E (128 * LDT)
#define STG_E  (4 * TILE_E)
#define PROJ_SMEM (2 * STG_E * 2)   // 81920 bytes

__device__ __forceinline__ void proj_load_stage(u32 sbase, int m0g, int n0g, int k0, int tid) {
    #pragma unroll
    for (int j = 0; j < 2; j++) {
        int id = tid + j * 256;
        int r  = id >> 2;
        int c  = (id & 3) * 8;
        u32 dst = sbase + 2 * (r * LDT + c);
        size_t gw = (size_t)(m0g + r) * CCH + k0 + c;
        size_t gx = (size_t)(n0g + r) * CCH + k0 + c;
        cpa16(dst,                  g_wh + gw);
        cpa16(dst + 2 * TILE_E,     g_wl + gw);
        cpa16(dst + 2 * 2 * TILE_E, g_xh + gx);
        cpa16(dst + 2 * 3 * TILE_E, g_xl + gx);
    }
    CPA_COMMIT();
}

__global__ void __launch_bounds__(256) proj_hmma_kernel(const float* __restrict__ pb,
                                                        float* __restrict__ out) {
    extern __shared__ __nv_bfloat16 psm[];
    const int tid  = threadIdx.x;
    const int wid  = tid >> 5;
    const int lane = tid & 31;
    const int wm   = wid >> 2;
    const int wn   = wid & 3;

    const int m0g = blockIdx.x * 128;
    const int n0g = blockIdx.y * 128;

    const u32 sb = smem_u32(psm);

    float acc[4][4][4];
    #pragma unroll
    for (int i = 0; i < 4; i++)
        #pragma unroll
        for (int j = 0; j < 4; j++)
            #pragma unroll
            for (int r = 0; r < 4; r++) acc[i][j][r] = 0.f;

    proj_load_stage(sb,             m0g, n0g, 0,  tid);
    proj_load_stage(sb + 2 * STG_E, m0g, n0g, 32, tid);

    const int arow = wm * 64 + (lane & 15);
    const int acol = (lane >> 4) * 8;
    const int brow = wn * 32 + (lane & 7);
    const int bcol = ((lane >> 3) & 1) * 8;

    #pragma unroll 1
    for (int kc = 0; kc < 16; kc++) {
        const int s = kc & 1;
        const u32 stg = sb + s * 2 * STG_E;
        if (kc < 15) { CPA_WAIT(1); } else { CPA_WAIT(0); }
        __syncthreads();

        const u32 whb = stg;
        const u32 wlb = stg + 2 * TILE_E;
        const u32 xhb = stg + 2 * 2 * TILE_E;
        const u32 xlb = stg + 2 * 3 * TILE_E;

        #pragma unroll
        for (int ks = 0; ks < 2; ks++) {
            const int kf = ks * 16;
            u32 ah[4][4], al[4][4], bh[4][2], bl[4][2];
            #pragma unroll
            for (int i = 0; i < 4; i++) {
                u32 ao = 2 * ((arow + i * 16) * LDT + acol + kf);
                ldmx4(ah[i], whb + ao);
                ldmx4(al[i], wlb + ao);
            }
            #pragma unroll
            for (int j = 0; j < 4; j++) {
                u32 bo = 2 * ((brow + j * 8) * LDT + bcol + kf);
                ldmx2(bh[j], xhb + bo);
                ldmx2(bl[j], xlb + bo);
            }
            #pragma unroll
            for (int i = 0; i < 4; i++)
                #pragma unroll
                for (int j = 0; j < 4; j++) {
                    mma16816(acc[i][j], ah[i], bh[j]);
                    mma16816(acc[i][j], ah[i], bl[j]);
                    mma16816(acc[i][j], al[i], bh[j]);
                }
        }
        __syncthreads();
        if (kc + 2 < 16) proj_load_stage(stg, m0g, n0g, (kc + 2) * 32, tid);
    }

    const int bb = n0g >> 14;
    const int hwb = (n0g & 16383) + wn * 32 + 2 * (lane & 3);
    #pragma unroll
    for (int i = 0; i < 4; i++) {
        int m = m0g + wm * 64 + i * 16 + (lane >> 2);
        float bias0 = pb[m];
        float bias8 = pb[m + 8];
        float* r0 = out + ((size_t)(bb * CCH + m)) * 16384 + hwb;
        float* r8 = out + ((size_t)(bb * CCH + m + 8)) * 16384 + hwb;
        #pragma unroll
        for (int j = 0; j < 4; j++) {
            float2 v0 = {acc[i][j][0] + bias0, acc[i][j][1] + bias0};
            float2 v1 = {acc[i][j][2] + bias8, acc[i][j][3] + bias8};
            *(float2*)(r0 + j * 8) = v0;
            *(float2*)(r8 + j * 8) = v1;
        }
    }
}

// ---------------------------------------------------------------------------
extern "C" void kernel_launch(void* const* d_in, const int* in_sizes, int n_in,
                              void* d_out, int out_size) {
    const float* qkv = (const float*)d_in[0];   // (4, 8, 192, 128, 128) f32
    const float* lsc = (const float*)d_in[1];   // (8,1,1) f32
    const float* rpb = (const float*)d_in[2];   // (225, 8) f32
    const float* pw  = (const float*)d_in[3];   // (512, 512) f32
    const float* pb  = (const float*)d_in[4];   // (512,) f32
    const int*   rel = (const int*)d_in[5];     // (64, 64) i32
    float* out = (float*)d_out;                 // (4, 512, 128, 128) f32

    cudaFuncSetAttribute(attn_kernel,
                         cudaFuncAttributeMaxDynamicSharedMemorySize, ATTN_SMEM);
    cudaFuncSetAttribute(proj_hmma_kernel,
                         cudaFuncAttributeMaxDynamicSharedMemorySize, PROJ_SMEM);

    bias_kernel<<<NHEAD * 64 * 64 / 256, 256>>>(rpb, rel);
    wsplit_kernel<<<CCH * CCH / 256, 256>>>(pw);
    attn_kernel<<<1024 * NHEAD, 128, ATTN_SMEM>>>(qkv, lsc);
    proj_hmma_kernel<<<dim3(CCH / 128, NPIX / 128), 256, PROJ_SMEM>>>(pb, out);
}

// round 6
// speedup vs baseline: 2.0419x; 1.1454x over previous
#include <cuda_runtime.h>
#include <cuda_bf16.h>
#include <cstdint>

// Problem constants (fixed shapes)
#define NHEAD 8
#define DH    64
#define HW_   128
#define NPIX  65536      // B*H*W
#define CCH   512        // channels

typedef unsigned long long u64;
typedef unsigned int u32;

// ---- scratch (allocation-free rule: __device__ globals) --------------------
__device__ __nv_bfloat16 g_xh[(size_t)NPIX * CCH];   // X hi, [pixel][channel]
__device__ __nv_bfloat16 g_xl[(size_t)NPIX * CCH];   // X lo
__device__ __nv_bfloat16 g_wh[CCH * CCH];            // W hi, row-major [m][k]
__device__ __nv_bfloat16 g_wl[CCH * CCH];            // W lo
__device__ float g_bias[NHEAD * 64 * 64];            // [head][q][k]

// ---- family-portable PTX helpers ------------------------------------------
__device__ __forceinline__ u32 smem_u32(const void* p) {
    u32 a; asm("{ .reg .u64 t; cvta.to.shared.u64 t, %1; cvt.u32.u64 %0, t; }"
               : "=r"(a) : "l"(p));
    return a;
}
__device__ __forceinline__ void cpa16(u32 dst, const void* src) {
    asm volatile("cp.async.cg.shared.global [%0], [%1], 16;" :: "r"(dst), "l"(src));
}
#define CPA_COMMIT() asm volatile("cp.async.commit_group;" ::: "memory")
#define CPA_WAIT(n)  asm volatile("cp.async.wait_group %0;" :: "n"(n) : "memory")

__device__ __forceinline__ void ldmx4(u32* r, u32 addr) {
    asm volatile("ldmatrix.sync.aligned.m8n8.x4.shared.b16 {%0,%1,%2,%3}, [%4];"
        : "=r"(r[0]), "=r"(r[1]), "=r"(r[2]), "=r"(r[3]) : "r"(addr));
}
__device__ __forceinline__ void ldmx2(u32* r, u32 addr) {
    asm volatile("ldmatrix.sync.aligned.m8n8.x2.shared.b16 {%0,%1}, [%2];"
        : "=r"(r[0]), "=r"(r[1]) : "r"(addr));
}
__device__ __forceinline__ void mma16816(float* c, const u32* a, const u32* b) {
    asm volatile("mma.sync.aligned.m16n8k16.row.col.f32.bf16.bf16.f32 "
        "{%0,%1,%2,%3}, {%4,%5,%6,%7}, {%8,%9}, {%0,%1,%2,%3};"
        : "+f"(c[0]), "+f"(c[1]), "+f"(c[2]), "+f"(c[3])
        : "r"(a[0]), "r"(a[1]), "r"(a[2]), "r"(a[3]), "r"(b[0]), "r"(b[1]));
}
// pack two fp32 -> bf16 pair (hi/lo split), packed for mma b16x2 registers
__device__ __forceinline__ void bfsplit2(float x0, float x1, u32& h, u32& l) {
    __nv_bfloat16 h0 = __float2bfloat16(x0);
    __nv_bfloat16 h1 = __float2bfloat16(x1);
    __nv_bfloat16 l0 = __float2bfloat16(x0 - __bfloat162float(h0));
    __nv_bfloat16 l1 = __float2bfloat16(x1 - __bfloat162float(h1));
    h = (u32)__bfloat16_as_ushort(h0) | ((u32)__bfloat16_as_ushort(h1) << 16);
    l = (u32)__bfloat16_as_ushort(l0) | ((u32)__bfloat16_as_ushort(l1) << 16);
}

// XOR-swizzled 64x64 bf16 tile: row*128B, 8 chunks of 16B, chunk ^= row&7.
// Conflict-free for both packed stores and ldmatrix.
#define SWZ(row, col) (((row) << 7) + (((((col) >> 3) ^ (row)) & 7) << 4) + (((col) & 7) << 1))

// ---------------------------------------------------------------------------
// Kernel: expand rpb_table via rel_index into [head][q][k]
// ---------------------------------------------------------------------------
__global__ void bias_kernel(const float* __restrict__ rpb, const int* __restrict__ rel) {
    int idx = blockIdx.x * blockDim.x + threadIdx.x;   // 32768
    if (idx >= NHEAD * 64 * 64) return;
    int h = idx >> 12;
    int r = idx & 4095;                                // q*64 + k
    g_bias[idx] = rpb[rel[r] * NHEAD + h];
}

// ---------------------------------------------------------------------------
// Kernel: split W (fp32) -> bf16 hi/lo
// ---------------------------------------------------------------------------
__global__ void __launch_bounds__(256) wsplit_kernel(const float* __restrict__ W) {
    int i = blockIdx.x * 256 + threadIdx.x;
    float x = W[i];
    __nv_bfloat16 h = __float2bfloat16(x);
    g_wh[i] = h;
    g_wl[i] = __float2bfloat16(x - __bfloat162float(h));
}

// ---------------------------------------------------------------------------
// Kernel: windowed cosine attention on mma.sync bf16 (hi/lo 4-term splits).
// Block = one (window, head), 128 threads / 4 warps; warp w = query rows 16w..
// Raw Q.K^T on tensor cores; cosine normalization + logit scale applied to
// S fragments (row/col inverse norms computed during load).
// ---------------------------------------------------------------------------
#define PADB 68
// smem byte offsets
#define QH_O  0
#define QL_O  8192
#define KH_O  16384
#define KL_O  24576
#define VH_O  32768
#define VL_O  40960
#define SB_O  49152          // 64*PADB*4 = 17408
#define PSQ_O 66560          // 128 floats (partial sumsq q)
#define PSK_O 67072          // 128 floats (partial sumsq k)
#define QSV_O 67584          // 64 floats: 1/|q_row|
#define KSV_O 67840          // 64 floats: 1/|k_row|
#define ATTN_SMEM 68096

__global__ void __launch_bounds__(128) attn_kernel(const float* __restrict__ qkv,
                                                   const float* __restrict__ lscale) {
    extern __shared__ char smem[];
    float* psq  = (float*)(smem + PSQ_O);
    float* psk  = (float*)(smem + PSK_O);
    float* qsv  = (float*)(smem + QSV_O);
    float* ksv  = (float*)(smem + KSV_O);
    float* sbias = (float*)(smem + SB_O);

    const int tid  = threadIdx.x;
    const int lane = tid & 31;
    const int wrp  = tid >> 5;

    const int wh   = blockIdx.x;
    const int head = wh & 7;
    const int win  = wh >> 3;
    const int b    = win >> 8;
    const int wy   = (win >> 4) & 15;
    const int wx   = win & 15;

    const float* base = qkv + (size_t)b * (NHEAD * 192 * 16384)
                            + (size_t)head * (192 * 16384)
                            + wy * 8 * HW_ + wx * 8;

    // ---- load + bf16 split + sumsq partials (no fp32 staging) ----
    {
        const int a = tid & 63;
        const int half = tid >> 6;             // 0 or 1
        const int d0 = half * 32;
        const int aoff = (a >> 3) * HW_ + (a & 7);
        float ssq = 0.f, ssk = 0.f;
        #pragma unroll 4
        for (int i = 0; i < 32; i += 2) {
            int d = d0 + i;
            int off = d * 16384 + aoff;
            float q0 = base[off];
            float q1 = base[off + 16384];
            float k0 = base[off + 64 * 16384];
            float k1 = base[off + 65 * 16384];
            float v0 = base[off + 128 * 16384];
            float v1 = base[off + 129 * 16384];
            ssq += q0 * q0 + q1 * q1;
            ssk += k0 * k0 + k1 * k1;
            u32 h_, l_;
            bfsplit2(q0, q1, h_, l_);
            *(u32*)(smem + QH_O + SWZ(a, d)) = h_;
            *(u32*)(smem + QL_O + SWZ(a, d)) = l_;
            bfsplit2(k0, k1, h_, l_);
            *(u32*)(smem + KH_O + SWZ(a, d)) = h_;
            *(u32*)(smem + KL_O + SWZ(a, d)) = l_;
            // v stored transposed: [d][a]
            __nv_bfloat16 vh0 = __float2bfloat16(v0);
            __nv_bfloat16 vh1 = __float2bfloat16(v1);
            *(__nv_bfloat16*)(smem + VH_O + SWZ(d, a))     = vh0;
            *(__nv_bfloat16*)(smem + VH_O + SWZ(d + 1, a)) = vh1;
            *(__nv_bfloat16*)(smem + VL_O + SWZ(d, a))     = __float2bfloat16(v0 - __bfloat162float(vh0));
            *(__nv_bfloat16*)(smem + VL_O + SWZ(d + 1, a)) = __float2bfloat16(v1 - __bfloat162float(vh1));
        }
        psq[half * 64 + a] = ssq;
        psk[half * 64 + a] = ssk;

        // bias tile for this head -> smem [q][PADB]
        const float4* gb4 = (const float4*)(g_bias + head * 4096);
        #pragma unroll
        for (int i = tid; i < 1024; i += 128) {
            float4 v4 = gb4[i];
            int q = i >> 4, k4 = (i & 15) * 4;
            *(float4*)&sbias[q * PADB + k4] = v4;
        }
    }
    __syncthreads();

    if (tid < 64) {
        qsv[tid] = 1.0f / fmaxf(sqrtf(psq[tid] + psq[tid + 64]), 1e-12f);
    } else {
        int a2 = tid - 64;
        ksv[a2] = 1.0f / fmaxf(sqrtf(psk[a2] + psk[a2 + 64]), 1e-12f);
    }
    __syncthreads();

    const u32 sb = smem_u32(smem);
    const int m0 = wrp * 16;
    const int arow = m0 + (lane & 15);
    const int acol = (lane >> 4) * 8;
    const int brl  = lane & 7;
    const int bcl  = ((lane >> 3) & 1) * 8;

    // ---- S = (Qh+Ql)(Kh+Kl)^T : acc[j][4], j = key n-tile (8 wide) ----
    float acc[8][4];
    #pragma unroll
    for (int j = 0; j < 8; j++)
        #pragma unroll
        for (int r = 0; r < 4; r++) acc[j][r] = 0.f;

    #pragma unroll
    for (int ks = 0; ks < 4; ks++) {
        const int kf = ks * 16;
        u32 aqh[4], aql[4];
        ldmx4(aqh, sb + QH_O + SWZ(arow, acol + kf));
        ldmx4(aql, sb + QL_O + SWZ(arow, acol + kf));
        #pragma unroll
        for (int j = 0; j < 8; j++) {
            u32 bkh[2], bkl[2];
            int krow = j * 8 + brl;
            ldmx2(bkh, sb + KH_O + SWZ(krow, bcl + kf));
            ldmx2(bkl, sb + KL_O + SWZ(krow, bcl + kf));
            mma16816(acc[j], aqh, bkh);
            mma16816(acc[j], aqh, bkl);
            mma16816(acc[j], aql, bkh);
            mma16816(acc[j], aql, bkl);
        }
    }

    // ---- cosine scale + bias + softmax on fragments ----
    const float sc = __expf(fminf(lscale[head], 4.6051702f));
    const int r0 = m0 + (lane >> 2);
    const int cb = 2 * (lane & 3);
    const float f0 = sc * qsv[r0];
    const float f1 = sc * qsv[r0 + 8];
    #pragma unroll
    for (int j = 0; j < 8; j++) {
        int c = 8 * j + cb;
        float kc0 = ksv[c], kc1 = ksv[c + 1];
        acc[j][0] = acc[j][0] * f0 * kc0 + sbias[r0 * PADB + c];
        acc[j][1] = acc[j][1] * f0 * kc1 + sbias[r0 * PADB + c + 1];
        acc[j][2] = acc[j][2] * f1 * kc0 + sbias[(r0 + 8) * PADB + c];
        acc[j][3] = acc[j][3] * f1 * kc1 + sbias[(r0 + 8) * PADB + c + 1];
    }
    float mx0 = -1e30f, mx1 = -1e30f;
    #pragma unroll
    for (int j = 0; j < 8; j++) {
        mx0 = fmaxf(mx0, fmaxf(acc[j][0], acc[j][1]));
        mx1 = fmaxf(mx1, fmaxf(acc[j][2], acc[j][3]));
    }
    mx0 = fmaxf(mx0, __shfl_xor_sync(0xffffffffu, mx0, 1));
    mx0 = fmaxf(mx0, __shfl_xor_sync(0xffffffffu, mx0, 2));
    mx1 = fmaxf(mx1, __shfl_xor_sync(0xffffffffu, mx1, 1));
    mx1 = fmaxf(mx1, __shfl_xor_sync(0xffffffffu, mx1, 2));
    float s0 = 0.f, s1 = 0.f;
    #pragma unroll
    for (int j = 0; j < 8; j++) {
        acc[j][0] = __expf(acc[j][0] - mx0); s0 += acc[j][0];
        acc[j][1] = __expf(acc[j][1] - mx0); s0 += acc[j][1];
        acc[j][2] = __expf(acc[j][2] - mx1); s1 += acc[j][2];
        acc[j][3] = __expf(acc[j][3] - mx1); s1 += acc[j][3];
    }
    s0 += __shfl_xor_sync(0xffffffffu, s0, 1);
    s0 += __shfl_xor_sync(0xffffffffu, s0, 2);
    s1 += __shfl_xor_sync(0xffffffffu, s1, 1);
    s1 += __shfl_xor_sync(0xffffffffu, s1, 2);
    const float inv0 = 1.0f / s0, inv1 = 1.0f / s1;
    #pragma unroll
    for (int j = 0; j < 8; j++) {
        acc[j][0] *= inv0; acc[j][1] *= inv0;
        acc[j][2] *= inv1; acc[j][3] *= inv1;
    }

    // ---- repack P C-fragments as A-fragments (in-register, FA2 identity) ----
    u32 aph[4][4], apl[4][4];
    #pragma unroll
    for (int kk = 0; kk < 4; kk++) {
        bfsplit2(acc[2 * kk][0],     acc[2 * kk][1],     aph[kk][0], apl[kk][0]);
        bfsplit2(acc[2 * kk][2],     acc[2 * kk][3],     aph[kk][1], apl[kk][1]);
        bfsplit2(acc[2 * kk + 1][0], acc[2 * kk + 1][1], aph[kk][2], apl[kk][2]);
        bfsplit2(acc[2 * kk + 1][2], acc[2 * kk + 1][3], aph[kk][3], apl[kk][3]);
    }

    // ---- O = (Ph+Pl)(Vh+Vl), V as B = [d][a] ----
    float o[8][4];
    #pragma unroll
    for (int j = 0; j < 8; j++)
        #pragma unroll
        for (int r = 0; r < 4; r++) o[j][r] = 0.f;

    #pragma unroll
    for (int ks = 0; ks < 4; ks++) {
        const int kf = ks * 16;
        #pragma unroll
        for (int jd = 0; jd < 8; jd++) {
            u32 bvh[2], bvl[2];
            int vrow = jd * 8 + brl;
            ldmx2(bvh, sb + VH_O + SWZ(vrow, bcl + kf));
            ldmx2(bvl, sb + VL_O + SWZ(vrow, bcl + kf));
            mma16816(o[jd], aph[ks], bvh);
            mma16816(o[jd], aph[ks], bvl);
            mma16816(o[jd], apl[ks], bvh);
            mma16816(o[jd], apl[ks], bvl);
        }
    }

    // ---- store O as bf16 hi/lo to X [pixel][channel] ----
    const int pr0 = b * 16384 + (wy * 8 + (r0 >> 3)) * HW_ + wx * 8 + (r0 & 7);
    const int r1 = r0 + 8;
    const int pr1 = b * 16384 + (wy * 8 + (r1 >> 3)) * HW_ + wx * 8 + (r1 & 7);
    const size_t x0 = (size_t)pr0 * CCH + head * 64;
    const size_t x1 = (size_t)pr1 * CCH + head * 64;
    #pragma unroll
    for (int j = 0; j < 8; j++) {
        int c = 8 * j + cb;
        u32 h0, l0, h1, l1;
        bfsplit2(o[j][0], o[j][1], h0, l0);
        bfsplit2(o[j][2], o[j][3], h1, l1);
        *(u32*)(g_xh + x0 + c) = h0;
        *(u32*)(g_xl + x0 + c) = l0;
        *(u32*)(g_xh + x1 + c) = h1;
        *(u32*)(g_xl + x1 + c) = l1;
    }
}

// ---------------------------------------------------------------------------
// Kernel: projection GEMM via mma.sync bf16 (3-split, fp32 accum).
// CTA: 128 channels (M) x 128 pixels (N), K=512 in 16 chunks of 32.
// ---------------------------------------------------------------------------
#define BK   32
#define LDT  40
#define TILE_E (128 * LDT)
#define STG_E  (4 * TILE_E)
#define PROJ_SMEM (2 * STG_E * 2)   // 81920 bytes

__device__ __forceinline__ void proj_load_stage(u32 sbase, int m0g, int n0g, int k0, int tid) {
    #pragma unroll
    for (int j = 0; j < 2; j++) {
        int id = tid + j * 256;
        int r  = id >> 2;
        int c  = (id & 3) * 8;
        u32 dst = sbase + 2 * (r * LDT + c);
        size_t gw = (size_t)(m0g + r) * CCH + k0 + c;
        size_t gx = (size_t)(n0g + r) * CCH + k0 + c;
        cpa16(dst,                  g_wh + gw);
        cpa16(dst + 2 * TILE_E,     g_wl + gw);
        cpa16(dst + 2 * 2 * TILE_E, g_xh + gx);
        cpa16(dst + 2 * 3 * TILE_E, g_xl + gx);
    }
    CPA_COMMIT();
}

__global__ void __launch_bounds__(256) proj_hmma_kernel(const float* __restrict__ pb,
                                                        float* __restrict__ out) {
    extern __shared__ __nv_bfloat16 psm[];
    const int tid  = threadIdx.x;
    const int wid  = tid >> 5;
    const int lane = tid & 31;
    const int wm   = wid >> 2;
    const int wn   = wid & 3;

    const int m0g = blockIdx.x * 128;
    const int n0g = blockIdx.y * 128;

    const u32 sb = smem_u32(psm);

    float acc[4][4][4];
    #pragma unroll
    for (int i = 0; i < 4; i++)
        #pragma unroll
        for (int j = 0; j < 4; j++)
            #pragma unroll
            for (int r = 0; r < 4; r++) acc[i][j][r] = 0.f;

    proj_load_stage(sb,             m0g, n0g, 0,  tid);
    proj_load_stage(sb + 2 * STG_E, m0g, n0g, 32, tid);

    const int arow = wm * 64 + (lane & 15);
    const int acol = (lane >> 4) * 8;
    const int brow = wn * 32 + (lane & 7);
    const int bcol = ((lane >> 3) & 1) * 8;

    #pragma unroll 1
    for (int kc = 0; kc < 16; kc++) {
        const int s = kc & 1;
        const u32 stg = sb + s * 2 * STG_E;
        if (kc < 15) { CPA_WAIT(1); } else { CPA_WAIT(0); }
        __syncthreads();

        const u32 whb = stg;
        const u32 wlb = stg + 2 * TILE_E;
        const u32 xhb = stg + 2 * 2 * TILE_E;
        const u32 xlb = stg + 2 * 3 * TILE_E;

        #pragma unroll
        for (int ks = 0; ks < 2; ks++) {
            const int kf = ks * 16;
            u32 ah[4][4], al[4][4], bh[4][2], bl[4][2];
            #pragma unroll
            for (int i = 0; i < 4; i++) {
                u32 ao = 2 * ((arow + i * 16) * LDT + acol + kf);
                ldmx4(ah[i], whb + ao);
                ldmx4(al[i], wlb + ao);
            }
            #pragma unroll
            for (int j = 0; j < 4; j++) {
                u32 bo = 2 * ((brow + j * 8) * LDT + bcol + kf);
                ldmx2(bh[j], xhb + bo);
                ldmx2(bl[j], xlb + bo);
            }
            #pragma unroll
            for (int i = 0; i < 4; i++)
                #pragma unroll
                for (int j = 0; j < 4; j++) {
                    mma16816(acc[i][j], ah[i], bh[j]);
                    mma16816(acc[i][j], ah[i], bl[j]);
                    mma16816(acc[i][j], al[i], bh[j]);
                }
        }
        __syncthreads();
        if (kc + 2 < 16) proj_load_stage(stg, m0g, n0g, (kc + 2) * 32, tid);
    }

    const int bb = n0g >> 14;
    const int hwb = (n0g & 16383) + wn * 32 + 2 * (lane & 3);
    #pragma unroll
    for (int i = 0; i < 4; i++) {
        int m = m0g + wm * 64 + i * 16 + (lane >> 2);
        float bias0 = pb[m];
        float bias8 = pb[m + 8];
        float* r0 = out + ((size_t)(bb * CCH + m)) * 16384 + hwb;
        float* r8 = out + ((size_t)(bb * CCH + m + 8)) * 16384 + hwb;
        #pragma unroll
        for (int j = 0; j < 4; j++) {
            float2 v0 = {acc[i][j][0] + bias0, acc[i][j][1] + bias0};
            float2 v1 = {acc[i][j][2] + bias8, acc[i][j][3] + bias8};
            *(float2*)(r0 + j * 8) = v0;
            *(float2*)(r8 + j * 8) = v1;
        }
    }
}

// ---------------------------------------------------------------------------
extern "C" void kernel_launch(void* const* d_in, const int* in_sizes, int n_in,
                              void* d_out, int out_size) {
    const float* qkv = (const float*)d_in[0];   // (4, 8, 192, 128, 128) f32
    const float* lsc = (const float*)d_in[1];   // (8,1,1) f32
    const float* rpb = (const float*)d_in[2];   // (225, 8) f32
    const float* pw  = (const float*)d_in[3];   // (512, 512) f32
    const float* pb  = (const float*)d_in[4];   // (512,) f32
    const int*   rel = (const int*)d_in[5];     // (64, 64) i32
    float* out = (float*)d_out;                 // (4, 512, 128, 128) f32

    cudaFuncSetAttribute(attn_kernel,
                         cudaFuncAttributeMaxDynamicSharedMemorySize, ATTN_SMEM);
    cudaFuncSetAttribute(proj_hmma_kernel,
                         cudaFuncAttributeMaxDynamicSharedMemorySize, PROJ_SMEM);

    bias_kernel<<<NHEAD * 64 * 64 / 256, 256>>>(rpb, rel);
    wsplit_kernel<<<CCH * CCH / 256, 256>>>(pw);
    attn_kernel<<<1024 * NHEAD, 128, ATTN_SMEM>>>(qkv, lsc);
    proj_hmma_kernel<<<dim3(CCH / 128, NPIX / 128), 256, PROJ_SMEM>>>(pb, out);
}

// round 7
// speedup vs baseline: 2.4398x; 1.1948x over previous
#include <cuda_runtime.h>
#include <cuda_bf16.h>
#include <cuda_fp16.h>
#include <cstdint>

// Problem constants (fixed shapes)
#define NHEAD 8
#define DH    64
#define HW_   128
#define NPIX  65536      // B*H*W
#define CCH   512        // channels

typedef unsigned long long u64;
typedef unsigned int u32;

// ---- scratch (allocation-free rule: __device__ globals) --------------------
__device__ __half g_xh[(size_t)NPIX * CCH];          // X hi (fp16), [pixel][channel]
__device__ __half g_xl[(size_t)NPIX * CCH];          // X lo (fp16)
__device__ __half g_w16[CCH * CCH];                  // W fp16, row-major [m][k]
__device__ float g_bias[NHEAD * 64 * 64];            // [head][q][k]

// ---- family-portable PTX helpers ------------------------------------------
__device__ __forceinline__ u32 smem_u32(const void* p) {
    u32 a; asm("{ .reg .u64 t; cvta.to.shared.u64 t, %1; cvt.u32.u64 %0, t; }"
               : "=r"(a) : "l"(p));
    return a;
}
__device__ __forceinline__ void cpa16(u32 dst, const void* src) {
    asm volatile("cp.async.cg.shared.global [%0], [%1], 16;" :: "r"(dst), "l"(src));
}
#define CPA_COMMIT() asm volatile("cp.async.commit_group;" ::: "memory")
#define CPA_WAIT(n)  asm volatile("cp.async.wait_group %0;" :: "n"(n) : "memory")

__device__ __forceinline__ void ldmx4(u32* r, u32 addr) {
    asm volatile("ldmatrix.sync.aligned.m8n8.x4.shared.b16 {%0,%1,%2,%3}, [%4];"
        : "=r"(r[0]), "=r"(r[1]), "=r"(r[2]), "=r"(r[3]) : "r"(addr));
}
__device__ __forceinline__ void ldmx2(u32* r, u32 addr) {
    asm volatile("ldmatrix.sync.aligned.m8n8.x2.shared.b16 {%0,%1}, [%2];"
        : "=r"(r[0]), "=r"(r[1]) : "r"(addr));
}
// bf16 mma (attention)
__device__ __forceinline__ void mma16816(float* c, const u32* a, const u32* b) {
    asm volatile("mma.sync.aligned.m16n8k16.row.col.f32.bf16.bf16.f32 "
        "{%0,%1,%2,%3}, {%4,%5,%6,%7}, {%8,%9}, {%0,%1,%2,%3};"
        : "+f"(c[0]), "+f"(c[1]), "+f"(c[2]), "+f"(c[3])
        : "r"(a[0]), "r"(a[1]), "r"(a[2]), "r"(a[3]), "r"(b[0]), "r"(b[1]));
}
// fp16 mma (projection)
__device__ __forceinline__ void mma16816h(float* c, const u32* a, const u32* b) {
    asm volatile("mma.sync.aligned.m16n8k16.row.col.f32.f16.f16.f32 "
        "{%0,%1,%2,%3}, {%4,%5,%6,%7}, {%8,%9}, {%0,%1,%2,%3};"
        : "+f"(c[0]), "+f"(c[1]), "+f"(c[2]), "+f"(c[3])
        : "r"(a[0]), "r"(a[1]), "r"(a[2]), "r"(a[3]), "r"(b[0]), "r"(b[1]));
}
// pack two fp32 -> bf16 pair (hi/lo split)
__device__ __forceinline__ void bfsplit2(float x0, float x1, u32& h, u32& l) {
    __nv_bfloat16 h0 = __float2bfloat16(x0);
    __nv_bfloat16 h1 = __float2bfloat16(x1);
    __nv_bfloat16 l0 = __float2bfloat16(x0 - __bfloat162float(h0));
    __nv_bfloat16 l1 = __float2bfloat16(x1 - __bfloat162float(h1));
    h = (u32)__bfloat16_as_ushort(h0) | ((u32)__bfloat16_as_ushort(h1) << 16);
    l = (u32)__bfloat16_as_ushort(l0) | ((u32)__bfloat16_as_ushort(l1) << 16);
}
// pack two fp32 -> fp16 pair (hi/lo split)
__device__ __forceinline__ void hsplit2(float x0, float x1, u32& h, u32& l) {
    __half h0 = __float2half_rn(x0);
    __half h1 = __float2half_rn(x1);
    __half l0 = __float2half_rn(x0 - __half2float(h0));
    __half l1 = __float2half_rn(x1 - __half2float(h1));
    h = (u32)__half_as_ushort(h0) | ((u32)__half_as_ushort(h1) << 16);
    l = (u32)__half_as_ushort(l0) | ((u32)__half_as_ushort(l1) << 16);
}

// XOR-swizzled 64x64 bf16 tile: row*128B, 8 chunks of 16B, chunk ^= row&7.
#define SWZ(row, col) (((row) << 7) + (((((col) >> 3) ^ (row)) & 7) << 4) + (((col) & 7) << 1))

// ---------------------------------------------------------------------------
// Kernel: expand rpb_table via rel_index into [head][q][k]
// ---------------------------------------------------------------------------
__global__ void bias_kernel(const float* __restrict__ rpb, const int* __restrict__ rel) {
    int idx = blockIdx.x * blockDim.x + threadIdx.x;   // 32768
    if (idx >= NHEAD * 64 * 64) return;
    int h = idx >> 12;
    int r = idx & 4095;                                // q*64 + k
    g_bias[idx] = rpb[rel[r] * NHEAD + h];
}

// ---------------------------------------------------------------------------
// Kernel: convert W (fp32) -> fp16
// ---------------------------------------------------------------------------
__global__ void __launch_bounds__(256) wconv_kernel(const float* __restrict__ W) {
    int i = blockIdx.x * 256 + threadIdx.x;
    g_w16[i] = __float2half_rn(W[i]);
}

// ---------------------------------------------------------------------------
// Kernel: windowed cosine attention on mma.sync bf16 (hi/lo 3-term splits).
// Block = one (window, head), 128 threads / 4 warps; warp w = query rows 16w..
// ---------------------------------------------------------------------------
#define PADB 68
// smem byte offsets
#define QH_O  0
#define QL_O  8192
#define KH_O  16384
#define KL_O  24576
#define VH_O  32768
#define VL_O  40960
#define SB_O  49152          // 64*PADB*4 = 17408
#define PSQ_O 66560          // 128 floats (partial sumsq q)
#define PSK_O 67072          // 128 floats (partial sumsq k)
#define QSV_O 67584          // 64 floats: 1/|q_row|
#define KSV_O 67840          // 64 floats: 1/|k_row|
#define ATTN_SMEM 68096

__global__ void __launch_bounds__(128) attn_kernel(const float* __restrict__ qkv,
                                                   const float* __restrict__ lscale) {
    extern __shared__ char smem[];
    float* psq  = (float*)(smem + PSQ_O);
    float* psk  = (float*)(smem + PSK_O);
    float* qsv  = (float*)(smem + QSV_O);
    float* ksv  = (float*)(smem + KSV_O);
    float* sbias = (float*)(smem + SB_O);

    const int tid  = threadIdx.x;
    const int lane = tid & 31;
    const int wrp  = tid >> 5;

    const int wh   = blockIdx.x;
    const int head = wh & 7;
    const int win  = wh >> 3;
    const int b    = win >> 8;
    const int wy   = (win >> 4) & 15;
    const int wx   = win & 15;

    const float* base = qkv + (size_t)b * (NHEAD * 192 * 16384)
                            + (size_t)head * (192 * 16384)
                            + wy * 8 * HW_ + wx * 8;

    // ---- load + bf16 split + sumsq partials ----
    {
        const int a = tid & 63;
        const int half_ = tid >> 6;             // 0 or 1
        const int d0 = half_ * 32;
        const int aoff = (a >> 3) * HW_ + (a & 7);
        float ssq = 0.f, ssk = 0.f;
        #pragma unroll 4
        for (int i = 0; i < 32; i += 2) {
            int d = d0 + i;
            int off = d * 16384 + aoff;
            float q0 = base[off];
            float q1 = base[off + 16384];
            float k0 = base[off + 64 * 16384];
            float k1 = base[off + 65 * 16384];
            float v0 = base[off + 128 * 16384];
            float v1 = base[off + 129 * 16384];
            ssq += q0 * q0 + q1 * q1;
            ssk += k0 * k0 + k1 * k1;
            u32 h_, l_;
            bfsplit2(q0, q1, h_, l_);
            *(u32*)(smem + QH_O + SWZ(a, d)) = h_;
            *(u32*)(smem + QL_O + SWZ(a, d)) = l_;
            bfsplit2(k0, k1, h_, l_);
            *(u32*)(smem + KH_O + SWZ(a, d)) = h_;
            *(u32*)(smem + KL_O + SWZ(a, d)) = l_;
            // v stored transposed: [d][a]
            __nv_bfloat16 vh0 = __float2bfloat16(v0);
            __nv_bfloat16 vh1 = __float2bfloat16(v1);
            *(__nv_bfloat16*)(smem + VH_O + SWZ(d, a))     = vh0;
            *(__nv_bfloat16*)(smem + VH_O + SWZ(d + 1, a)) = vh1;
            *(__nv_bfloat16*)(smem + VL_O + SWZ(d, a))     = __float2bfloat16(v0 - __bfloat162float(vh0));
            *(__nv_bfloat16*)(smem + VL_O + SWZ(d + 1, a)) = __float2bfloat16(v1 - __bfloat162float(vh1));
        }
        psq[half_ * 64 + a] = ssq;
        psk[half_ * 64 + a] = ssk;

        // bias tile for this head -> smem [q][PADB]
        const float4* gb4 = (const float4*)(g_bias + head * 4096);
        #pragma unroll
        for (int i = tid; i < 1024; i += 128) {
            float4 v4 = gb4[i];
            int q = i >> 4, k4 = (i & 15) * 4;
            *(float4*)&sbias[q * PADB + k4] = v4;
        }
    }
    __syncthreads();

    if (tid < 64) {
        qsv[tid] = 1.0f / fmaxf(sqrtf(psq[tid] + psq[tid + 64]), 1e-12f);
    } else {
        int a2 = tid - 64;
        ksv[a2] = 1.0f / fmaxf(sqrtf(psk[a2] + psk[a2 + 64]), 1e-12f);
    }
    __syncthreads();

    const u32 sb = smem_u32(smem);
    const int m0 = wrp * 16;
    const int arow = m0 + (lane & 15);
    const int acol = (lane >> 4) * 8;
    const int brl  = lane & 7;
    const int bcl  = ((lane >> 3) & 1) * 8;

    // ---- S = QK^T, 3-term split ----
    float acc[8][4];
    #pragma unroll
    for (int j = 0; j < 8; j++)
        #pragma unroll
        for (int r = 0; r < 4; r++) acc[j][r] = 0.f;

    #pragma unroll
    for (int ks = 0; ks < 4; ks++) {
        const int kf = ks * 16;
        u32 aqh[4], aql[4];
        ldmx4(aqh, sb + QH_O + SWZ(arow, acol + kf));
        ldmx4(aql, sb + QL_O + SWZ(arow, acol + kf));
        #pragma unroll
        for (int j = 0; j < 8; j++) {
            u32 bkh[2], bkl[2];
            int krow = j * 8 + brl;
            ldmx2(bkh, sb + KH_O + SWZ(krow, bcl + kf));
            ldmx2(bkl, sb + KL_O + SWZ(krow, bcl + kf));
            mma16816(acc[j], aqh, bkh);
            mma16816(acc[j], aqh, bkl);
            mma16816(acc[j], aql, bkh);
        }
    }

    // ---- cosine scale + bias + softmax ----
    const float sc = __expf(fminf(lscale[head], 4.6051702f));
    const int r0 = m0 + (lane >> 2);
    const int cb = 2 * (lane & 3);
    const float f0 = sc * qsv[r0];
    const float f1 = sc * qsv[r0 + 8];
    #pragma unroll
    for (int j = 0; j < 8; j++) {
        int c = 8 * j + cb;
        float kc0 = ksv[c], kc1 = ksv[c + 1];
        acc[j][0] = acc[j][0] * f0 * kc0 + sbias[r0 * PADB + c];
        acc[j][1] = acc[j][1] * f0 * kc1 + sbias[r0 * PADB + c + 1];
        acc[j][2] = acc[j][2] * f1 * kc0 + sbias[(r0 + 8) * PADB + c];
        acc[j][3] = acc[j][3] * f1 * kc1 + sbias[(r0 + 8) * PADB + c + 1];
    }
    float mx0 = -1e30f, mx1 = -1e30f;
    #pragma unroll
    for (int j = 0; j < 8; j++) {
        mx0 = fmaxf(mx0, fmaxf(acc[j][0], acc[j][1]));
        mx1 = fmaxf(mx1, fmaxf(acc[j][2], acc[j][3]));
    }
    mx0 = fmaxf(mx0, __shfl_xor_sync(0xffffffffu, mx0, 1));
    mx0 = fmaxf(mx0, __shfl_xor_sync(0xffffffffu, mx0, 2));
    mx1 = fmaxf(mx1, __shfl_xor_sync(0xffffffffu, mx1, 1));
    mx1 = fmaxf(mx1, __shfl_xor_sync(0xffffffffu, mx1, 2));
    float s0 = 0.f, s1 = 0.f;
    #pragma unroll
    for (int j = 0; j < 8; j++) {
        acc[j][0] = __expf(acc[j][0] - mx0); s0 += acc[j][0];
        acc[j][1] = __expf(acc[j][1] - mx0); s0 += acc[j][1];
        acc[j][2] = __expf(acc[j][2] - mx1); s1 += acc[j][2];
        acc[j][3] = __expf(acc[j][3] - mx1); s1 += acc[j][3];
    }
    s0 += __shfl_xor_sync(0xffffffffu, s0, 1);
    s0 += __shfl_xor_sync(0xffffffffu, s0, 2);
    s1 += __shfl_xor_sync(0xffffffffu, s1, 1);
    s1 += __shfl_xor_sync(0xffffffffu, s1, 2);
    const float inv0 = 1.0f / s0, inv1 = 1.0f / s1;
    #pragma unroll
    for (int j = 0; j < 8; j++) {
        acc[j][0] *= inv0; acc[j][1] *= inv0;
        acc[j][2] *= inv1; acc[j][3] *= inv1;
    }

    // ---- repack P C-fragments as A-fragments ----
    u32 aph[4][4], apl[4][4];
    #pragma unroll
    for (int kk = 0; kk < 4; kk++) {
        bfsplit2(acc[2 * kk][0],     acc[2 * kk][1],     aph[kk][0], apl[kk][0]);
        bfsplit2(acc[2 * kk][2],     acc[2 * kk][3],     aph[kk][1], apl[kk][1]);
        bfsplit2(acc[2 * kk + 1][0], acc[2 * kk + 1][1], aph[kk][2], apl[kk][2]);
        bfsplit2(acc[2 * kk + 1][2], acc[2 * kk + 1][3], aph[kk][3], apl[kk][3]);
    }

    // ---- O = P.V, 3-term ----
    float o[8][4];
    #pragma unroll
    for (int j = 0; j < 8; j++)
        #pragma unroll
        for (int r = 0; r < 4; r++) o[j][r] = 0.f;

    #pragma unroll
    for (int ks = 0; ks < 4; ks++) {
        const int kf = ks * 16;
        #pragma unroll
        for (int jd = 0; jd < 8; jd++) {
            u32 bvh[2], bvl[2];
            int vrow = jd * 8 + brl;
            ldmx2(bvh, sb + VH_O + SWZ(vrow, bcl + kf));
            ldmx2(bvl, sb + VL_O + SWZ(vrow, bcl + kf));
            mma16816(o[jd], aph[ks], bvh);
            mma16816(o[jd], aph[ks], bvl);
            mma16816(o[jd], apl[ks], bvh);
        }
    }

    // ---- store O as fp16 hi/lo to X [pixel][channel] ----
    const int pr0 = b * 16384 + (wy * 8 + (r0 >> 3)) * HW_ + wx * 8 + (r0 & 7);
    const int r1 = r0 + 8;
    const int pr1 = b * 16384 + (wy * 8 + (r1 >> 3)) * HW_ + wx * 8 + (r1 & 7);
    const size_t x0 = (size_t)pr0 * CCH + head * 64;
    const size_t x1 = (size_t)pr1 * CCH + head * 64;
    #pragma unroll
    for (int j = 0; j < 8; j++) {
        int c = 8 * j + cb;
        u32 h0, l0, h1, l1;
        hsplit2(o[j][0], o[j][1], h0, l0);
        hsplit2(o[j][2], o[j][3], h1, l1);
        *(u32*)(g_xh + x0 + c) = h0;
        *(u32*)(g_xl + x0 + c) = l0;
        *(u32*)(g_xh + x1 + c) = h1;
        *(u32*)(g_xl + x1 + c) = l1;
    }
}

// ---------------------------------------------------------------------------
// Kernel: projection GEMM via mma.sync fp16, 2-term (W16·Xh + W16·Xl).
// CTA: 128 channels (M) x 128 pixels (N), K=512 in 16 chunks of 32.
// ---------------------------------------------------------------------------
#define LDT  40
#define TILE_B (128 * LDT * 2)      // 10240 bytes per tile
#define STG_B  (3 * TILE_B)         // Wh | Xh | Xl
#define PROJ_SMEM (2 * STG_B)       // 61440 bytes

__device__ __forceinline__ void proj_load_stage(u32 sbase, int m0g, int n0g, int k0, int tid) {
    #pragma unroll
    for (int j = 0; j < 2; j++) {
        int id = tid + j * 256;
        int r  = id >> 2;
        int c  = (id & 3) * 8;
        u32 dst = sbase + 2 * (r * LDT + c);
        size_t gw = (size_t)(m0g + r) * CCH + k0 + c;
        size_t gx = (size_t)(n0g + r) * CCH + k0 + c;
        cpa16(dst,              g_w16 + gw);
        cpa16(dst + TILE_B,     g_xh + gx);
        cpa16(dst + 2 * TILE_B, g_xl + gx);
    }
    CPA_COMMIT();
}

__global__ void __launch_bounds__(256) proj_hmma_kernel(const float* __restrict__ pb,
                                                        float* __restrict__ out) {
    extern __shared__ __half psm[];
    const int tid  = threadIdx.x;
    const int wid  = tid >> 5;
    const int lane = tid & 31;
    const int wm   = wid >> 2;
    const int wn   = wid & 3;

    const int m0g = blockIdx.x * 128;
    const int n0g = blockIdx.y * 128;

    const u32 sb = smem_u32(psm);

    float acc[4][4][4];
    #pragma unroll
    for (int i = 0; i < 4; i++)
        #pragma unroll
        for (int j = 0; j < 4; j++)
            #pragma unroll
            for (int r = 0; r < 4; r++) acc[i][j][r] = 0.f;

    proj_load_stage(sb,         m0g, n0g, 0,  tid);
    proj_load_stage(sb + STG_B, m0g, n0g, 32, tid);

    const int arow = wm * 64 + (lane & 15);
    const int acol = (lane >> 4) * 8;
    const int brow = wn * 32 + (lane & 7);
    const int bcol = ((lane >> 3) & 1) * 8;

    #pragma unroll 1
    for (int kc = 0; kc < 16; kc++) {
        const int s = kc & 1;
        const u32 stg = sb + s * STG_B;
        if (kc < 15) { CPA_WAIT(1); } else { CPA_WAIT(0); }
        __syncthreads();

        const u32 whb = stg;
        const u32 xhb = stg + TILE_B;
        const u32 xlb = stg + 2 * TILE_B;

        #pragma unroll
        for (int ks = 0; ks < 2; ks++) {
            const int kf = ks * 16;
            u32 ah[4][4], bh[4][2], bl[4][2];
            #pragma unroll
            for (int i = 0; i < 4; i++) {
                u32 ao = 2 * ((arow + i * 16) * LDT + acol + kf);
                ldmx4(ah[i], whb + ao);
            }
            #pragma unroll
            for (int j = 0; j < 4; j++) {
                u32 bo = 2 * ((brow + j * 8) * LDT + bcol + kf);
                ldmx2(bh[j], xhb + bo);
                ldmx2(bl[j], xlb + bo);
            }
            #pragma unroll
            for (int i = 0; i < 4; i++)
                #pragma unroll
                for (int j = 0; j < 4; j++) {
                    mma16816h(acc[i][j], ah[i], bh[j]);
                    mma16816h(acc[i][j], ah[i], bl[j]);
                }
        }
        __syncthreads();
        if (kc + 2 < 16) proj_load_stage(stg, m0g, n0g, (kc + 2) * 32, tid);
    }

    const int bb = n0g >> 14;
    const int hwb = (n0g & 16383) + wn * 32 + 2 * (lane & 3);
    #pragma unroll
    for (int i = 0; i < 4; i++) {
        int m = m0g + wm * 64 + i * 16 + (lane >> 2);
        float bias0 = pb[m];
        float bias8 = pb[m + 8];
        float* r0 = out + ((size_t)(bb * CCH + m)) * 16384 + hwb;
        float* r8 = out + ((size_t)(bb * CCH + m + 8)) * 16384 + hwb;
        #pragma unroll
        for (int j = 0; j < 4; j++) {
            float2 v0 = {acc[i][j][0] + bias0, acc[i][j][1] + bias0};
            float2 v1 = {acc[i][j][2] + bias8, acc[i][j][3] + bias8};
            *(float2*)(r0 + j * 8) = v0;
            *(float2*)(r8 + j * 8) = v1;
        }
    }
}

// ---------------------------------------------------------------------------
extern "C" void kernel_launch(void* const* d_in, const int* in_sizes, int n_in,
                              void* d_out, int out_size) {
    const float* qkv = (const float*)d_in[0];   // (4, 8, 192, 128, 128) f32
    const float* lsc = (const float*)d_in[1];   // (8,1,1) f32
    const float* rpb = (const float*)d_in[2];   // (225, 8) f32
    const float* pw  = (const float*)d_in[3];   // (512, 512) f32
    const float* pb  = (const float*)d_in[4];   // (512,) f32
    const int*   rel = (const int*)d_in[5];     // (64, 64) i32
    float* out = (float*)d_out;                 // (4, 512, 128, 128) f32

    cudaFuncSetAttribute(attn_kernel,
                         cudaFuncAttributeMaxDynamicSharedMemorySize, ATTN_SMEM);
    cudaFuncSetAttribute(proj_hmma_kernel,
                         cudaFuncAttributeMaxDynamicSharedMemorySize, PROJ_SMEM);

    bias_kernel<<<NHEAD * 64 * 64 / 256, 256>>>(rpb, rel);
    wconv_kernel<<<CCH * CCH / 256, 256>>>(pw);
    attn_kernel<<<1024 * NHEAD, 128, ATTN_SMEM>>>(qkv, lsc);
    proj_hmma_kernel<<<dim3(CCH / 128, NPIX / 128), 256, PROJ_SMEM>>>(pb, out);
}

// round 8
// speedup vs baseline: 3.2087x; 1.3152x over previous
#include <cuda_runtime.h>
#include <cuda_bf16.h>
#include <cuda_fp16.h>
#include <cstdint>

// Problem constants (fixed shapes)
#define NHEAD 8
#define DH    64
#define HW_   128
#define NPIX  65536      // B*H*W
#define CCH   512        // channels

typedef unsigned long long u64;
typedef unsigned int u32;

// ---- scratch (allocation-free rule: __device__ globals) --------------------
__device__ __half g_xh[(size_t)NPIX * CCH];          // X (fp16), [pixel][channel]
__device__ __half g_w16[CCH * CCH];                  // W fp16, row-major [m][k]
__device__ float g_bias[NHEAD * 64 * 64];            // [head][q][k]

// ---- family-portable PTX helpers ------------------------------------------
__device__ __forceinline__ u32 smem_u32(const void* p) {
    u32 a; asm("{ .reg .u64 t; cvta.to.shared.u64 t, %1; cvt.u32.u64 %0, t; }"
               : "=r"(a) : "l"(p));
    return a;
}
__device__ __forceinline__ void cpa16(u32 dst, const void* src) {
    asm volatile("cp.async.cg.shared.global [%0], [%1], 16;" :: "r"(dst), "l"(src));
}
#define CPA_COMMIT() asm volatile("cp.async.commit_group;" ::: "memory")
#define CPA_WAIT(n)  asm volatile("cp.async.wait_group %0;" :: "n"(n) : "memory")

__device__ __forceinline__ void ldmx4(u32* r, u32 addr) {
    asm volatile("ldmatrix.sync.aligned.m8n8.x4.shared.b16 {%0,%1,%2,%3}, [%4];"
        : "=r"(r[0]), "=r"(r[1]), "=r"(r[2]), "=r"(r[3]) : "r"(addr));
}
__device__ __forceinline__ void ldmx2(u32* r, u32 addr) {
    asm volatile("ldmatrix.sync.aligned.m8n8.x2.shared.b16 {%0,%1}, [%2];"
        : "=r"(r[0]), "=r"(r[1]) : "r"(addr));
}
// bf16 mma (attention)
__device__ __forceinline__ void mma16816(float* c, const u32* a, const u32* b) {
    asm volatile("mma.sync.aligned.m16n8k16.row.col.f32.bf16.bf16.f32 "
        "{%0,%1,%2,%3}, {%4,%5,%6,%7}, {%8,%9}, {%0,%1,%2,%3};"
        : "+f"(c[0]), "+f"(c[1]), "+f"(c[2]), "+f"(c[3])
        : "r"(a[0]), "r"(a[1]), "r"(a[2]), "r"(a[3]), "r"(b[0]), "r"(b[1]));
}
// fp16 mma (projection)
__device__ __forceinline__ void mma16816h(float* c, const u32* a, const u32* b) {
    asm volatile("mma.sync.aligned.m16n8k16.row.col.f32.f16.f16.f32 "
        "{%0,%1,%2,%3}, {%4,%5,%6,%7}, {%8,%9}, {%0,%1,%2,%3};"
        : "+f"(c[0]), "+f"(c[1]), "+f"(c[2]), "+f"(c[3])
        : "r"(a[0]), "r"(a[1]), "r"(a[2]), "r"(a[3]), "r"(b[0]), "r"(b[1]));
}
// pack two fp32 -> bf16 pair (hi/lo split)
__device__ __forceinline__ void bfsplit2(float x0, float x1, u32& h, u32& l) {
    __nv_bfloat16 h0 = __float2bfloat16(x0);
    __nv_bfloat16 h1 = __float2bfloat16(x1);
    __nv_bfloat16 l0 = __float2bfloat16(x0 - __bfloat162float(h0));
    __nv_bfloat16 l1 = __float2bfloat16(x1 - __bfloat162float(h1));
    h = (u32)__bfloat16_as_ushort(h0) | ((u32)__bfloat16_as_ushort(h1) << 16);
    l = (u32)__bfloat16_as_ushort(l0) | ((u32)__bfloat16_as_ushort(l1) << 16);
}
// pack two fp32 -> fp16 pair
__device__ __forceinline__ u32 hpack2(float x0, float x1) {
    __half2 h = __floats2half2_rn(x0, x1);
    return *(u32*)&h;
}

// XOR-swizzled 64x64 bf16 tile: row*128B, 8 chunks of 16B, chunk ^= row&7.
#define SWZ(row, col) (((row) << 7) + (((((col) >> 3) ^ (row)) & 7) << 4) + (((col) & 7) << 1))

// ---------------------------------------------------------------------------
// Kernel: expand rpb_table via rel_index into [head][q][k]
// ---------------------------------------------------------------------------
__global__ void bias_kernel(const float* __restrict__ rpb, const int* __restrict__ rel) {
    int idx = blockIdx.x * blockDim.x + threadIdx.x;   // 32768
    if (idx >= NHEAD * 64 * 64) return;
    int h = idx >> 12;
    int r = idx & 4095;                                // q*64 + k
    g_bias[idx] = rpb[rel[r] * NHEAD + h];
}

// ---------------------------------------------------------------------------
// Kernel: convert W (fp32) -> fp16
// ---------------------------------------------------------------------------
__global__ void __launch_bounds__(256) wconv_kernel(const float* __restrict__ W) {
    int i = blockIdx.x * 256 + threadIdx.x;
    g_w16[i] = __float2half_rn(W[i]);
}

// ---------------------------------------------------------------------------
// Kernel: windowed cosine attention on mma.sync bf16 (hi/lo 3-term splits).
// Block = one (window, head), 128 threads / 4 warps; warp w = query rows 16w..
// ---------------------------------------------------------------------------
#define PADB 68
// smem byte offsets
#define QH_O  0
#define QL_O  8192
#define KH_O  16384
#define KL_O  24576
#define VH_O  32768
#define VL_O  40960
#define SB_O  49152          // 64*PADB*4 = 17408
#define PSQ_O 66560          // 128 floats (partial sumsq q)
#define PSK_O 67072          // 128 floats (partial sumsq k)
#define QSV_O 67584          // 64 floats: 1/|q_row|
#define KSV_O 67840          // 64 floats: 1/|k_row|
#define ATTN_SMEM 68096

__global__ void __launch_bounds__(128) attn_kernel(const float* __restrict__ qkv,
                                                   const float* __restrict__ lscale) {
    extern __shared__ char smem[];
    float* psq  = (float*)(smem + PSQ_O);
    float* psk  = (float*)(smem + PSK_O);
    float* qsv  = (float*)(smem + QSV_O);
    float* ksv  = (float*)(smem + KSV_O);
    float* sbias = (float*)(smem + SB_O);

    const int tid  = threadIdx.x;
    const int lane = tid & 31;
    const int wrp  = tid >> 5;

    const int wh   = blockIdx.x;
    const int head = wh & 7;
    const int win  = wh >> 3;
    const int b    = win >> 8;
    const int wy   = (win >> 4) & 15;
    const int wx   = win & 15;

    const float* base = qkv + (size_t)b * (NHEAD * 192 * 16384)
                            + (size_t)head * (192 * 16384)
                            + wy * 8 * HW_ + wx * 8;

    // ---- load + bf16 split + sumsq partials ----
    {
        const int a = tid & 63;
        const int half_ = tid >> 6;             // 0 or 1
        const int d0 = half_ * 32;
        const int aoff = (a >> 3) * HW_ + (a & 7);
        float ssq = 0.f, ssk = 0.f;
        #pragma unroll 4
        for (int i = 0; i < 32; i += 2) {
            int d = d0 + i;
            int off = d * 16384 + aoff;
            float q0 = base[off];
            float q1 = base[off + 16384];
            float k0 = base[off + 64 * 16384];
            float k1 = base[off + 65 * 16384];
            float v0 = base[off + 128 * 16384];
            float v1 = base[off + 129 * 16384];
            ssq += q0 * q0 + q1 * q1;
            ssk += k0 * k0 + k1 * k1;
            u32 h_, l_;
            bfsplit2(q0, q1, h_, l_);
            *(u32*)(smem + QH_O + SWZ(a, d)) = h_;
            *(u32*)(smem + QL_O + SWZ(a, d)) = l_;
            bfsplit2(k0, k1, h_, l_);
            *(u32*)(smem + KH_O + SWZ(a, d)) = h_;
            *(u32*)(smem + KL_O + SWZ(a, d)) = l_;
            // v stored transposed: [d][a]
            __nv_bfloat16 vh0 = __float2bfloat16(v0);
            __nv_bfloat16 vh1 = __float2bfloat16(v1);
            *(__nv_bfloat16*)(smem + VH_O + SWZ(d, a))     = vh0;
            *(__nv_bfloat16*)(smem + VH_O + SWZ(d + 1, a)) = vh1;
            *(__nv_bfloat16*)(smem + VL_O + SWZ(d, a))     = __float2bfloat16(v0 - __bfloat162float(vh0));
            *(__nv_bfloat16*)(smem + VL_O + SWZ(d + 1, a)) = __float2bfloat16(v1 - __bfloat162float(vh1));
        }
        psq[half_ * 64 + a] = ssq;
        psk[half_ * 64 + a] = ssk;

        // bias tile for this head -> smem [q][PADB]
        const float4* gb4 = (const float4*)(g_bias + head * 4096);
        #pragma unroll
        for (int i = tid; i < 1024; i += 128) {
            float4 v4 = gb4[i];
            int q = i >> 4, k4 = (i & 15) * 4;
            *(float4*)&sbias[q * PADB + k4] = v4;
        }
    }
    __syncthreads();

    if (tid < 64) {
        qsv[tid] = 1.0f / fmaxf(sqrtf(psq[tid] + psq[tid + 64]), 1e-12f);
    } else {
        int a2 = tid - 64;
        ksv[a2] = 1.0f / fmaxf(sqrtf(psk[a2] + psk[a2 + 64]), 1e-12f);
    }
    __syncthreads();

    const u32 sb = smem_u32(smem);
    const int m0 = wrp * 16;
    const int arow = m0 + (lane & 15);
    const int acol = (lane >> 4) * 8;
    const int brl  = lane & 7;
    const int bcl  = ((lane >> 3) & 1) * 8;

    // ---- S = QK^T, 3-term split ----
    float acc[8][4];
    #pragma unroll
    for (int j = 0; j < 8; j++)
        #pragma unroll
        for (int r = 0; r < 4; r++) acc[j][r] = 0.f;

    #pragma unroll
    for (int ks = 0; ks < 4; ks++) {
        const int kf = ks * 16;
        u32 aqh[4], aql[4];
        ldmx4(aqh, sb + QH_O + SWZ(arow, acol + kf));
        ldmx4(aql, sb + QL_O + SWZ(arow, acol + kf));
        #pragma unroll
        for (int j = 0; j < 8; j++) {
            u32 bkh[2], bkl[2];
            int krow = j * 8 + brl;
            ldmx2(bkh, sb + KH_O + SWZ(krow, bcl + kf));
            ldmx2(bkl, sb + KL_O + SWZ(krow, bcl + kf));
            mma16816(acc[j], aqh, bkh);
            mma16816(acc[j], aqh, bkl);
            mma16816(acc[j], aql, bkh);
        }
    }

    // ---- cosine scale + bias + softmax ----
    const float sc = __expf(fminf(lscale[head], 4.6051702f));
    const int r0 = m0 + (lane >> 2);
    const int cb = 2 * (lane & 3);
    const float f0 = sc * qsv[r0];
    const float f1 = sc * qsv[r0 + 8];
    #pragma unroll
    for (int j = 0; j < 8; j++) {
        int c = 8 * j + cb;
        float kc0 = ksv[c], kc1 = ksv[c + 1];
        acc[j][0] = acc[j][0] * f0 * kc0 + sbias[r0 * PADB + c];
        acc[j][1] = acc[j][1] * f0 * kc1 + sbias[r0 * PADB + c + 1];
        acc[j][2] = acc[j][2] * f1 * kc0 + sbias[(r0 + 8) * PADB + c];
        acc[j][3] = acc[j][3] * f1 * kc1 + sbias[(r0 + 8) * PADB + c + 1];
    }
    float mx0 = -1e30f, mx1 = -1e30f;
    #pragma unroll
    for (int j = 0; j < 8; j++) {
        mx0 = fmaxf(mx0, fmaxf(acc[j][0], acc[j][1]));
        mx1 = fmaxf(mx1, fmaxf(acc[j][2], acc[j][3]));
    }
    mx0 = fmaxf(mx0, __shfl_xor_sync(0xffffffffu, mx0, 1));
    mx0 = fmaxf(mx0, __shfl_xor_sync(0xffffffffu, mx0, 2));
    mx1 = fmaxf(mx1, __shfl_xor_sync(0xffffffffu, mx1, 1));
    mx1 = fmaxf(mx1, __shfl_xor_sync(0xffffffffu, mx1, 2));
    float s0 = 0.f, s1 = 0.f;
    #pragma unroll
    for (int j = 0; j < 8; j++) {
        acc[j][0] = __expf(acc[j][0] - mx0); s0 += acc[j][0];
        acc[j][1] = __expf(acc[j][1] - mx0); s0 += acc[j][1];
        acc[j][2] = __expf(acc[j][2] - mx1); s1 += acc[j][2];
        acc[j][3] = __expf(acc[j][3] - mx1); s1 += acc[j][3];
    }
    s0 += __shfl_xor_sync(0xffffffffu, s0, 1);
    s0 += __shfl_xor_sync(0xffffffffu, s0, 2);
    s1 += __shfl_xor_sync(0xffffffffu, s1, 1);
    s1 += __shfl_xor_sync(0xffffffffu, s1, 2);
    const float inv0 = 1.0f / s0, inv1 = 1.0f / s1;
    #pragma unroll
    for (int j = 0; j < 8; j++) {
        acc[j][0] *= inv0; acc[j][1] *= inv0;
        acc[j][2] *= inv1; acc[j][3] *= inv1;
    }

    // ---- repack P C-fragments as A-fragments ----
    u32 aph[4][4], apl[4][4];
    #pragma unroll
    for (int kk = 0; kk < 4; kk++) {
        bfsplit2(acc[2 * kk][0],     acc[2 * kk][1],     aph[kk][0], apl[kk][0]);
        bfsplit2(acc[2 * kk][2],     acc[2 * kk][3],     aph[kk][1], apl[kk][1]);
        bfsplit2(acc[2 * kk + 1][0], acc[2 * kk + 1][1], aph[kk][2], apl[kk][2]);
        bfsplit2(acc[2 * kk + 1][2], acc[2 * kk + 1][3], aph[kk][3], apl[kk][3]);
    }

    // ---- O = P.V, 3-term ----
    float o[8][4];
    #pragma unroll
    for (int j = 0; j < 8; j++)
        #pragma unroll
        for (int r = 0; r < 4; r++) o[j][r] = 0.f;

    #pragma unroll
    for (int ks = 0; ks < 4; ks++) {
        const int kf = ks * 16;
        #pragma unroll
        for (int jd = 0; jd < 8; jd++) {
            u32 bvh[2], bvl[2];
            int vrow = jd * 8 + brl;
            ldmx2(bvh, sb + VH_O + SWZ(vrow, bcl + kf));
            ldmx2(bvl, sb + VL_O + SWZ(vrow, bcl + kf));
            mma16816(o[jd], aph[ks], bvh);
            mma16816(o[jd], aph[ks], bvl);
            mma16816(o[jd], apl[ks], bvh);
        }
    }

    // ---- store O as fp16 to X [pixel][channel] ----
    const int pr0 = b * 16384 + (wy * 8 + (r0 >> 3)) * HW_ + wx * 8 + (r0 & 7);
    const int r1 = r0 + 8;
    const int pr1 = b * 16384 + (wy * 8 + (r1 >> 3)) * HW_ + wx * 8 + (r1 & 7);
    const size_t x0 = (size_t)pr0 * CCH + head * 64;
    const size_t x1 = (size_t)pr1 * CCH + head * 64;
    #pragma unroll
    for (int j = 0; j < 8; j++) {
        int c = 8 * j + cb;
        *(u32*)(g_xh + x0 + c) = hpack2(o[j][0], o[j][1]);
        *(u32*)(g_xh + x1 + c) = hpack2(o[j][2], o[j][3]);
    }
}

// ---------------------------------------------------------------------------
// Kernel: projection GEMM via mma.sync fp16, single term (W16 · X16).
// CTA: 128 channels (M) x 128 pixels (N), K=512 in 8 chunks of 64.
// ---------------------------------------------------------------------------
#define LDT2 72                      // 64 + 8 pad (fp16 units)
#define PTILE_B (128 * LDT2 * 2)     // 18432 bytes per tile
#define PSTG_B  (2 * PTILE_B)        // W | X = 36864
#define PROJ_SMEM (2 * PSTG_B)       // 73728 bytes

__device__ __forceinline__ void proj_load_stage(u32 sbase, int m0g, int n0g, int k0, int tid) {
    #pragma unroll
    for (int j = 0; j < 4; j++) {
        int id = tid + j * 256;          // 0..1023
        int r  = id >> 3;                // row 0..127
        int c  = (id & 7) * 8;           // col (fp16)
        u32 dst = sbase + 2 * (r * LDT2 + c);
        cpa16(dst,           g_w16 + (size_t)(m0g + r) * CCH + k0 + c);
        cpa16(dst + PTILE_B, g_xh  + (size_t)(n0g + r) * CCH + k0 + c);
    }
    CPA_COMMIT();
}

__global__ void __launch_bounds__(256) proj_hmma_kernel(const float* __restrict__ pb,
                                                        float* __restrict__ out) {
    extern __shared__ __half psm[];
    const int tid  = threadIdx.x;
    const int wid  = tid >> 5;
    const int lane = tid & 31;
    const int wm   = wid >> 2;
    const int wn   = wid & 3;

    const int m0g = blockIdx.x * 128;
    const int n0g = blockIdx.y * 128;

    const u32 sb = smem_u32(psm);

    float acc[4][4][4];
    #pragma unroll
    for (int i = 0; i < 4; i++)
        #pragma unroll
        for (int j = 0; j < 4; j++)
            #pragma unroll
            for (int r = 0; r < 4; r++) acc[i][j][r] = 0.f;

    proj_load_stage(sb,          m0g, n0g, 0,  tid);
    proj_load_stage(sb + PSTG_B, m0g, n0g, 64, tid);

    const int arow = wm * 64 + (lane & 15);
    const int acol = (lane >> 4) * 8;
    const int brow = wn * 32 + (lane & 7);
    const int bcol = ((lane >> 3) & 1) * 8;

    #pragma unroll 1
    for (int kc = 0; kc < 8; kc++) {
        const u32 stg = sb + (kc & 1) * PSTG_B;
        if (kc < 7) { CPA_WAIT(1); } else { CPA_WAIT(0); }
        __syncthreads();

        const u32 whb = stg;
        const u32 xhb = stg + PTILE_B;

        #pragma unroll
        for (int ks = 0; ks < 4; ks++) {
            const int kf = ks * 16;
            u32 ah[4][4], bh[4][2];
            #pragma unroll
            for (int i = 0; i < 4; i++)
                ldmx4(ah[i], whb + 2 * ((arow + i * 16) * LDT2 + acol + kf));
            #pragma unroll
            for (int j = 0; j < 4; j++)
                ldmx2(bh[j], xhb + 2 * ((brow + j * 8) * LDT2 + bcol + kf));
            #pragma unroll
            for (int i = 0; i < 4; i++)
                #pragma unroll
                for (int j = 0; j < 4; j++)
                    mma16816h(acc[i][j], ah[i], bh[j]);
        }
        __syncthreads();
        if (kc + 2 < 8) proj_load_stage(stg, m0g, n0g, (kc + 2) * 64, tid);
    }

    const int bb = n0g >> 14;
    const int hwb = (n0g & 16383) + wn * 32 + 2 * (lane & 3);
    #pragma unroll
    for (int i = 0; i < 4; i++) {
        int m = m0g + wm * 64 + i * 16 + (lane >> 2);
        float bias0 = pb[m];
        float bias8 = pb[m + 8];
        float* r0 = out + ((size_t)(bb * CCH + m)) * 16384 + hwb;
        float* r8 = out + ((size_t)(bb * CCH + m + 8)) * 16384 + hwb;
        #pragma unroll
        for (int j = 0; j < 4; j++) {
            float2 v0 = {acc[i][j][0] + bias0, acc[i][j][1] + bias0};
            float2 v1 = {acc[i][j][2] + bias8, acc[i][j][3] + bias8};
            *(float2*)(r0 + j * 8) = v0;
            *(float2*)(r8 + j * 8) = v1;
        }
    }
}

// ---------------------------------------------------------------------------
extern "C" void kernel_launch(void* const* d_in, const int* in_sizes, int n_in,
                              void* d_out, int out_size) {
    const float* qkv = (const float*)d_in[0];   // (4, 8, 192, 128, 128) f32
    const float* lsc = (const float*)d_in[1];   // (8,1,1) f32
    const float* rpb = (const float*)d_in[2];   // (225, 8) f32
    const float* pw  = (const float*)d_in[3];   // (512, 512) f32
    const float* pb  = (const float*)d_in[4];   // (512,) f32
    const int*   rel = (const int*)d_in[5];     // (64, 64) i32
    float* out = (float*)d_out;                 // (4, 512, 128, 128) f32

    cudaFuncSetAttribute(attn_kernel,
                         cudaFuncAttributeMaxDynamicSharedMemorySize, ATTN_SMEM);
    cudaFuncSetAttribute(proj_hmma_kernel,
                         cudaFuncAttributeMaxDynamicSharedMemorySize, PROJ_SMEM);

    bias_kernel<<<NHEAD * 64 * 64 / 256, 256>>>(rpb, rel);
    wconv_kernel<<<CCH * CCH / 256, 256>>>(pw);
    attn_kernel<<<1024 * NHEAD, 128, ATTN_SMEM>>>(qkv, lsc);
    proj_hmma_kernel<<<dim3(CCH / 128, NPIX / 128), 256, PROJ_SMEM>>>(pb, out);
}

// round 9
// speedup vs baseline: 3.4167x; 1.0648x over previous
#include <cuda_runtime.h>
#include <cuda_bf16.h>
#include <cuda_fp16.h>
#include <cstdint>

// Problem constants (fixed shapes)
#define NHEAD 8
#define DH    64
#define HW_   128
#define NPIX  65536      // B*H*W
#define CCH   512        // channels

typedef unsigned long long u64;
typedef unsigned int u32;

// ---- scratch (allocation-free rule: __device__ globals) --------------------
__device__ __half g_xh[(size_t)NPIX * CCH];          // X (fp16), [pixel][channel]
__device__ __half g_w16[CCH * CCH];                  // W fp16, row-major [m][k]
__device__ float g_bias[NHEAD * 64 * 64];            // [head][q][k]

// ---- family-portable PTX helpers ------------------------------------------
__device__ __forceinline__ u32 smem_u32(const void* p) {
    u32 a; asm("{ .reg .u64 t; cvta.to.shared.u64 t, %1; cvt.u32.u64 %0, t; }"
               : "=r"(a) : "l"(p));
    return a;
}
__device__ __forceinline__ void cpa16(u32 dst, const void* src) {
    asm volatile("cp.async.cg.shared.global [%0], [%1], 16;" :: "r"(dst), "l"(src));
}
#define CPA_COMMIT() asm volatile("cp.async.commit_group;" ::: "memory")
#define CPA_WAIT(n)  asm volatile("cp.async.wait_group %0;" :: "n"(n) : "memory")

__device__ __forceinline__ void ldmx4(u32* r, u32 addr) {
    asm volatile("ldmatrix.sync.aligned.m8n8.x4.shared.b16 {%0,%1,%2,%3}, [%4];"
        : "=r"(r[0]), "=r"(r[1]), "=r"(r[2]), "=r"(r[3]) : "r"(addr));
}
__device__ __forceinline__ void ldmx2(u32* r, u32 addr) {
    asm volatile("ldmatrix.sync.aligned.m8n8.x2.shared.b16 {%0,%1}, [%2];"
        : "=r"(r[0]), "=r"(r[1]) : "r"(addr));
}
__device__ __forceinline__ void ldmx2t(u32* r, u32 addr) {
    asm volatile("ldmatrix.sync.aligned.m8n8.x2.trans.shared.b16 {%0,%1}, [%2];"
        : "=r"(r[0]), "=r"(r[1]) : "r"(addr));
}
// bf16 mma (attention)
__device__ __forceinline__ void mma16816(float* c, const u32* a, const u32* b) {
    asm volatile("mma.sync.aligned.m16n8k16.row.col.f32.bf16.bf16.f32 "
        "{%0,%1,%2,%3}, {%4,%5,%6,%7}, {%8,%9}, {%0,%1,%2,%3};"
        : "+f"(c[0]), "+f"(c[1]), "+f"(c[2]), "+f"(c[3])
        : "r"(a[0]), "r"(a[1]), "r"(a[2]), "r"(a[3]), "r"(b[0]), "r"(b[1]));
}
// fp16 mma (projection)
__device__ __forceinline__ void mma16816h(float* c, const u32* a, const u32* b) {
    asm volatile("mma.sync.aligned.m16n8k16.row.col.f32.f16.f16.f32 "
        "{%0,%1,%2,%3}, {%4,%5,%6,%7}, {%8,%9}, {%0,%1,%2,%3};"
        : "+f"(c[0]), "+f"(c[1]), "+f"(c[2]), "+f"(c[3])
        : "r"(a[0]), "r"(a[1]), "r"(a[2]), "r"(a[3]), "r"(b[0]), "r"(b[1]));
}
// pack two fp32 -> bf16 pair (hi/lo split)
__device__ __forceinline__ void bfsplit2(float x0, float x1, u32& h, u32& l) {
    __nv_bfloat16 h0 = __float2bfloat16(x0);
    __nv_bfloat16 h1 = __float2bfloat16(x1);
    __nv_bfloat16 l0 = __float2bfloat16(x0 - __bfloat162float(h0));
    __nv_bfloat16 l1 = __float2bfloat16(x1 - __bfloat162float(h1));
    h = (u32)__bfloat16_as_ushort(h0) | ((u32)__bfloat16_as_ushort(h1) << 16);
    l = (u32)__bfloat16_as_ushort(l0) | ((u32)__bfloat16_as_ushort(l1) << 16);
}
// pack two fp32 -> fp16 pair
__device__ __forceinline__ u32 hpack2(float x0, float x1) {
    __half2 h = __floats2half2_rn(x0, x1);
    return *(u32*)&h;
}

// XOR-swizzled 64x64 bf16 tile: row*128B, 8 chunks of 16B, chunk ^= row&7.
#define SWZ(row, col) (((row) << 7) + (((((col) >> 3) ^ (row)) & 7) << 4) + (((col) & 7) << 1))

// ---------------------------------------------------------------------------
// Kernel: expand rpb_table via rel_index into [head][q][k]
// ---------------------------------------------------------------------------
__global__ void bias_kernel(const float* __restrict__ rpb, const int* __restrict__ rel) {
    int idx = blockIdx.x * blockDim.x + threadIdx.x;   // 32768
    if (idx >= NHEAD * 64 * 64) return;
    int h = idx >> 12;
    int r = idx & 4095;                                // q*64 + k
    g_bias[idx] = rpb[rel[r] * NHEAD + h];
}

// ---------------------------------------------------------------------------
// Kernel: convert W (fp32) -> fp16
// ---------------------------------------------------------------------------
__global__ void __launch_bounds__(256) wconv_kernel(const float* __restrict__ W) {
    int i = blockIdx.x * 256 + threadIdx.x;
    g_w16[i] = __float2half_rn(W[i]);
}

// ---------------------------------------------------------------------------
// Kernel: windowed cosine attention on mma.sync bf16 (hi/lo 3-term splits).
// Block = one (window, head), 128 threads / 4 warps; warp w = query rows 16w..
// All of q/k/v stored [a][d] swizzled; V read via ldmatrix.trans for PV.
// ---------------------------------------------------------------------------
// smem byte offsets
#define QH_O  0
#define QL_O  8192
#define KH_O  16384
#define KL_O  24576
#define VH_O  32768
#define VL_O  40960
#define PSQ_O 49152          // 128 floats
#define PSK_O 49664          // 128 floats
#define QSV_O 50176          // 64 floats: 1/|q_row|
#define KSV_O 50432          // 64 floats: 1/|k_row|
#define ATTN_SMEM 50688

__global__ void __launch_bounds__(128, 4) attn_kernel(const float* __restrict__ qkv,
                                                      const float* __restrict__ lscale) {
    extern __shared__ char smem[];
    float* psq  = (float*)(smem + PSQ_O);
    float* psk  = (float*)(smem + PSK_O);
    float* qsv  = (float*)(smem + QSV_O);
    float* ksv  = (float*)(smem + KSV_O);

    const int tid  = threadIdx.x;
    const int lane = tid & 31;
    const int wrp  = tid >> 5;

    const int wh   = blockIdx.x;
    const int head = wh & 7;
    const int win  = wh >> 3;
    const int b    = win >> 8;
    const int wy   = (win >> 4) & 15;
    const int wx   = win & 15;

    const float* base = qkv + (size_t)b * (NHEAD * 192 * 16384)
                            + (size_t)head * (192 * 16384)
                            + wy * 8 * HW_ + wx * 8;

    // ---- load + bf16 split + sumsq partials ----
    {
        const int a = tid & 63;
        const int half_ = tid >> 6;             // 0 or 1
        const int d0 = half_ * 32;
        const int aoff = (a >> 3) * HW_ + (a & 7);
        float ssq = 0.f, ssk = 0.f;
        #pragma unroll 4
        for (int i = 0; i < 32; i += 2) {
            int d = d0 + i;
            int off = d * 16384 + aoff;
            float q0 = base[off];
            float q1 = base[off + 16384];
            float k0 = base[off + 64 * 16384];
            float k1 = base[off + 65 * 16384];
            float v0 = base[off + 128 * 16384];
            float v1 = base[off + 129 * 16384];
            ssq += q0 * q0 + q1 * q1;
            ssk += k0 * k0 + k1 * k1;
            u32 h_, l_;
            bfsplit2(q0, q1, h_, l_);
            *(u32*)(smem + QH_O + SWZ(a, d)) = h_;
            *(u32*)(smem + QL_O + SWZ(a, d)) = l_;
            bfsplit2(k0, k1, h_, l_);
            *(u32*)(smem + KH_O + SWZ(a, d)) = h_;
            *(u32*)(smem + KL_O + SWZ(a, d)) = l_;
            bfsplit2(v0, v1, h_, l_);
            *(u32*)(smem + VH_O + SWZ(a, d)) = h_;
            *(u32*)(smem + VL_O + SWZ(a, d)) = l_;
        }
        psq[half_ * 64 + a] = ssq;
        psk[half_ * 64 + a] = ssk;
    }
    __syncthreads();

    if (tid < 64) {
        qsv[tid] = 1.0f / fmaxf(sqrtf(psq[tid] + psq[tid + 64]), 1e-12f);
    } else {
        int a2 = tid - 64;
        ksv[a2] = 1.0f / fmaxf(sqrtf(psk[a2] + psk[a2 + 64]), 1e-12f);
    }
    __syncthreads();

    const u32 sb = smem_u32(smem);
    const int m0 = wrp * 16;
    const int arow = m0 + (lane & 15);
    const int acol = (lane >> 4) * 8;
    const int brl  = lane & 7;
    const int bcl  = ((lane >> 3) & 1) * 8;
    const int trl  = lane & 15;            // trans ldmatrix source row within 16-k chunk

    const int r0 = m0 + (lane >> 2);
    const int cb = 2 * (lane & 3);

    // ---- prefetch bias fragments (L2-resident; hides under QK MMAs) ----
    float2 bf0[8], bf1[8];
    {
        const float2* gb = (const float2*)(g_bias + head * 4096);
        #pragma unroll
        for (int j = 0; j < 8; j++) {
            bf0[j] = gb[r0 * 32 + j * 4 + (lane & 3)];
            bf1[j] = gb[(r0 + 8) * 32 + j * 4 + (lane & 3)];
        }
    }

    // ---- S = QK^T, 3-term split ----
    float acc[8][4];
    #pragma unroll
    for (int j = 0; j < 8; j++)
        #pragma unroll
        for (int r = 0; r < 4; r++) acc[j][r] = 0.f;

    #pragma unroll
    for (int ks = 0; ks < 4; ks++) {
        const int kf = ks * 16;
        u32 aqh[4], aql[4];
        ldmx4(aqh, sb + QH_O + SWZ(arow, acol + kf));
        ldmx4(aql, sb + QL_O + SWZ(arow, acol + kf));
        #pragma unroll
        for (int j = 0; j < 8; j++) {
            u32 bkh[2], bkl[2];
            int krow = j * 8 + brl;
            ldmx2(bkh, sb + KH_O + SWZ(krow, bcl + kf));
            ldmx2(bkl, sb + KL_O + SWZ(krow, bcl + kf));
            mma16816(acc[j], aqh, bkh);
            mma16816(acc[j], aqh, bkl);
            mma16816(acc[j], aql, bkh);
        }
    }

    // ---- cosine scale + bias + softmax ----
    const float sc = __expf(fminf(lscale[head], 4.6051702f));
    const float f0 = sc * qsv[r0];
    const float f1 = sc * qsv[r0 + 8];
    #pragma unroll
    for (int j = 0; j < 8; j++) {
        int c = 8 * j + cb;
        float kc0 = ksv[c], kc1 = ksv[c + 1];
        acc[j][0] = acc[j][0] * f0 * kc0 + bf0[j].x;
        acc[j][1] = acc[j][1] * f0 * kc1 + bf0[j].y;
        acc[j][2] = acc[j][2] * f1 * kc0 + bf1[j].x;
        acc[j][3] = acc[j][3] * f1 * kc1 + bf1[j].y;
    }
    float mx0 = -1e30f, mx1 = -1e30f;
    #pragma unroll
    for (int j = 0; j < 8; j++) {
        mx0 = fmaxf(mx0, fmaxf(acc[j][0], acc[j][1]));
        mx1 = fmaxf(mx1, fmaxf(acc[j][2], acc[j][3]));
    }
    mx0 = fmaxf(mx0, __shfl_xor_sync(0xffffffffu, mx0, 1));
    mx0 = fmaxf(mx0, __shfl_xor_sync(0xffffffffu, mx0, 2));
    mx1 = fmaxf(mx1, __shfl_xor_sync(0xffffffffu, mx1, 1));
    mx1 = fmaxf(mx1, __shfl_xor_sync(0xffffffffu, mx1, 2));
    float s0 = 0.f, s1 = 0.f;
    #pragma unroll
    for (int j = 0; j < 8; j++) {
        acc[j][0] = __expf(acc[j][0] - mx0); s0 += acc[j][0];
        acc[j][1] = __expf(acc[j][1] - mx0); s0 += acc[j][1];
        acc[j][2] = __expf(acc[j][2] - mx1); s1 += acc[j][2];
        acc[j][3] = __expf(acc[j][3] - mx1); s1 += acc[j][3];
    }
    s0 += __shfl_xor_sync(0xffffffffu, s0, 1);
    s0 += __shfl_xor_sync(0xffffffffu, s0, 2);
    s1 += __shfl_xor_sync(0xffffffffu, s1, 1);
    s1 += __shfl_xor_sync(0xffffffffu, s1, 2);
    const float inv0 = 1.0f / s0, inv1 = 1.0f / s1;
    #pragma unroll
    for (int j = 0; j < 8; j++) {
        acc[j][0] *= inv0; acc[j][1] *= inv0;
        acc[j][2] *= inv1; acc[j][3] *= inv1;
    }

    // ---- repack P C-fragments as A-fragments ----
    u32 aph[4][4], apl[4][4];
    #pragma unroll
    for (int kk = 0; kk < 4; kk++) {
        bfsplit2(acc[2 * kk][0],     acc[2 * kk][1],     aph[kk][0], apl[kk][0]);
        bfsplit2(acc[2 * kk][2],     acc[2 * kk][3],     aph[kk][1], apl[kk][1]);
        bfsplit2(acc[2 * kk + 1][0], acc[2 * kk + 1][1], aph[kk][2], apl[kk][2]);
        bfsplit2(acc[2 * kk + 1][2], acc[2 * kk + 1][3], aph[kk][3], apl[kk][3]);
    }

    // ---- O = P.V, 3-term; V [a][d] read via ldmatrix.trans ----
    float o[8][4];
    #pragma unroll
    for (int j = 0; j < 8; j++)
        #pragma unroll
        for (int r = 0; r < 4; r++) o[j][r] = 0.f;

    #pragma unroll
    for (int ks = 0; ks < 4; ks++) {
        const int kf = ks * 16;
        #pragma unroll
        for (int jd = 0; jd < 8; jd++) {
            u32 bvh[2], bvl[2];
            u32 bo = SWZ(kf + trl, jd * 8);
            ldmx2t(bvh, sb + VH_O + bo);
            ldmx2t(bvl, sb + VL_O + bo);
            mma16816(o[jd], aph[ks], bvh);
            mma16816(o[jd], aph[ks], bvl);
            mma16816(o[jd], apl[ks], bvh);
        }
    }

    // ---- store O as fp16 to X [pixel][channel] ----
    const int pr0 = b * 16384 + (wy * 8 + (r0 >> 3)) * HW_ + wx * 8 + (r0 & 7);
    const int r1 = r0 + 8;
    const int pr1 = b * 16384 + (wy * 8 + (r1 >> 3)) * HW_ + wx * 8 + (r1 & 7);
    const size_t x0 = (size_t)pr0 * CCH + head * 64;
    const size_t x1 = (size_t)pr1 * CCH + head * 64;
    #pragma unroll
    for (int j = 0; j < 8; j++) {
        int c = 8 * j + cb;
        *(u32*)(g_xh + x0 + c) = hpack2(o[j][0], o[j][1]);
        *(u32*)(g_xh + x1 + c) = hpack2(o[j][2], o[j][3]);
    }
}

// ---------------------------------------------------------------------------
// Kernel: projection GEMM via mma.sync fp16, single term (W16 · X16).
// CTA: 128 channels (M) x 128 pixels (N), K=512 in 8 chunks of 64.
// ---------------------------------------------------------------------------
#define LDT2 72                      // 64 + 8 pad (fp16 units)
#define PTILE_B (128 * LDT2 * 2)     // 18432 bytes per tile
#define PSTG_B  (2 * PTILE_B)        // W | X = 36864
#define PROJ_SMEM (2 * PSTG_B)       // 73728 bytes

__device__ __forceinline__ void proj_load_stage(u32 sbase, int m0g, int n0g, int k0, int tid) {
    #pragma unroll
    for (int j = 0; j < 4; j++) {
        int id = tid + j * 256;          // 0..1023
        int r  = id >> 3;                // row 0..127
        int c  = (id & 7) * 8;           // col (fp16)
        u32 dst = sbase + 2 * (r * LDT2 + c);
        cpa16(dst,           g_w16 + (size_t)(m0g + r) * CCH + k0 + c);
        cpa16(dst + PTILE_B, g_xh  + (size_t)(n0g + r) * CCH + k0 + c);
    }
    CPA_COMMIT();
}

__global__ void __launch_bounds__(256) proj_hmma_kernel(const float* __restrict__ pb,
                                                        float* __restrict__ out) {
    extern __shared__ __half psm[];
    const int tid  = threadIdx.x;
    const int wid  = tid >> 5;
    const int lane = tid & 31;
    const int wm   = wid >> 2;
    const int wn   = wid & 3;

    const int m0g = blockIdx.x * 128;
    const int n0g = blockIdx.y * 128;

    const u32 sb = smem_u32(psm);

    float acc[4][4][4];
    #pragma unroll
    for (int i = 0; i < 4; i++)
        #pragma unroll
        for (int j = 0; j < 4; j++)
            #pragma unroll
            for (int r = 0; r < 4; r++) acc[i][j][r] = 0.f;

    proj_load_stage(sb,          m0g, n0g, 0,  tid);
    proj_load_stage(sb + PSTG_B, m0g, n0g, 64, tid);

    const int arow = wm * 64 + (lane & 15);
    const int acol = (lane >> 4) * 8;
    const int brow = wn * 32 + (lane & 7);
    const int bcol = ((lane >> 3) & 1) * 8;

    #pragma unroll 1
    for (int kc = 0; kc < 8; kc++) {
        const u32 stg = sb + (kc & 1) * PSTG_B;
        if (kc < 7) { CPA_WAIT(1); } else { CPA_WAIT(0); }
        __syncthreads();

        const u32 whb = stg;
        const u32 xhb = stg + PTILE_B;

        #pragma unroll
        for (int ks = 0; ks < 4; ks++) {
            const int kf = ks * 16;
            u32 ah[4][4], bh[4][2];
            #pragma unroll
            for (int i = 0; i < 4; i++)
                ldmx4(ah[i], whb + 2 * ((arow + i * 16) * LDT2 + acol + kf));
            #pragma unroll
            for (int j = 0; j < 4; j++)
                ldmx2(bh[j], xhb + 2 * ((brow + j * 8) * LDT2 + bcol + kf));
            #pragma unroll
            for (int i = 0; i < 4; i++)
                #pragma unroll
                for (int j = 0; j < 4; j++)
                    mma16816h(acc[i][j], ah[i], bh[j]);
        }
        __syncthreads();
        if (kc + 2 < 8) proj_load_stage(stg, m0g, n0g, (kc + 2) * 64, tid);
    }

    const int bb = n0g >> 14;
    const int hwb = (n0g & 16383) + wn * 32 + 2 * (lane & 3);
    #pragma unroll
    for (int i = 0; i < 4; i++) {
        int m = m0g + wm * 64 + i * 16 + (lane >> 2);
        float bias0 = pb[m];
        float bias8 = pb[m + 8];
        float* r0 = out + ((size_t)(bb * CCH + m)) * 16384 + hwb;
        float* r8 = out + ((size_t)(bb * CCH + m + 8)) * 16384 + hwb;
        #pragma unroll
        for (int j = 0; j < 4; j++) {
            float2 v0 = {acc[i][j][0] + bias0, acc[i][j][1] + bias0};
            float2 v1 = {acc[i][j][2] + bias8, acc[i][j][3] + bias8};
            *(float2*)(r0 + j * 8) = v0;
            *(float2*)(r8 + j * 8) = v1;
        }
    }
}

// ---------------------------------------------------------------------------
extern "C" void kernel_launch(void* const* d_in, const int* in_sizes, int n_in,
                              void* d_out, int out_size) {
    const float* qkv = (const float*)d_in[0];   // (4, 8, 192, 128, 128) f32
    const float* lsc = (const float*)d_in[1];   // (8,1,1) f32
    const float* rpb = (const float*)d_in[2];   // (225, 8) f32
    const float* pw  = (const float*)d_in[3];   // (512, 512) f32
    const float* pb  = (const float*)d_in[4];   // (512,) f32
    const int*   rel = (const int*)d_in[5];     // (64, 64) i32
    float* out = (float*)d_out;                 // (4, 512, 128, 128) f32

    cudaFuncSetAttribute(attn_kernel,
                         cudaFuncAttributeMaxDynamicSharedMemorySize, ATTN_SMEM);
    cudaFuncSetAttribute(proj_hmma_kernel,
                         cudaFuncAttributeMaxDynamicSharedMemorySize, PROJ_SMEM);

    bias_kernel<<<NHEAD * 64 * 64 / 256, 256>>>(rpb, rel);
    wconv_kernel<<<CCH * CCH / 256, 256>>>(pw);
    attn_kernel<<<1024 * NHEAD, 128, ATTN_SMEM>>>(qkv, lsc);
    proj_hmma_kernel<<<dim3(CCH / 128, NPIX / 128), 256, PROJ_SMEM>>>(pb, out);
}

// round 10
// speedup vs baseline: 4.1544x; 1.2159x over previous
#include <cuda_runtime.h>
#include <cuda_bf16.h>
#include <cuda_fp16.h>
#include <cstdint>

// Problem constants (fixed shapes)
#define NHEAD 8
#define DH    64
#define HW_   128
#define NPIX  65536      // B*H*W
#define CCH   512        // channels

typedef unsigned long long u64;
typedef unsigned int u32;

// ---- scratch (allocation-free rule: __device__ globals) --------------------
__device__ __half g_xh[(size_t)NPIX * CCH];          // X (fp16), [pixel][channel]
__device__ __half g_w16[CCH * CCH];                  // W fp16, row-major [m][k]
__device__ float g_bias[NHEAD * 64 * 64];            // [head][q][k]

// ---- family-portable PTX helpers ------------------------------------------
__device__ __forceinline__ u32 smem_u32(const void* p) {
    u32 a; asm("{ .reg .u64 t; cvta.to.shared.u64 t, %1; cvt.u32.u64 %0, t; }"
               : "=r"(a) : "l"(p));
    return a;
}
__device__ __forceinline__ void cpa16(u32 dst, const void* src) {
    asm volatile("cp.async.cg.shared.global [%0], [%1], 16;" :: "r"(dst), "l"(src));
}
#define CPA_COMMIT() asm volatile("cp.async.commit_group;" ::: "memory")
#define CPA_WAIT(n)  asm volatile("cp.async.wait_group %0;" :: "n"(n) : "memory")

__device__ __forceinline__ void ldmx4(u32* r, u32 addr) {
    asm volatile("ldmatrix.sync.aligned.m8n8.x4.shared.b16 {%0,%1,%2,%3}, [%4];"
        : "=r"(r[0]), "=r"(r[1]), "=r"(r[2]), "=r"(r[3]) : "r"(addr));
}
__device__ __forceinline__ void ldmx2(u32* r, u32 addr) {
    asm volatile("ldmatrix.sync.aligned.m8n8.x2.shared.b16 {%0,%1}, [%2];"
        : "=r"(r[0]), "=r"(r[1]) : "r"(addr));
}
__device__ __forceinline__ void ldmx2t(u32* r, u32 addr) {
    asm volatile("ldmatrix.sync.aligned.m8n8.x2.trans.shared.b16 {%0,%1}, [%2];"
        : "=r"(r[0]), "=r"(r[1]) : "r"(addr));
}
// bf16 mma (attention)
__device__ __forceinline__ void mma16816(float* c, const u32* a, const u32* b) {
    asm volatile("mma.sync.aligned.m16n8k16.row.col.f32.bf16.bf16.f32 "
        "{%0,%1,%2,%3}, {%4,%5,%6,%7}, {%8,%9}, {%0,%1,%2,%3};"
        : "+f"(c[0]), "+f"(c[1]), "+f"(c[2]), "+f"(c[3])
        : "r"(a[0]), "r"(a[1]), "r"(a[2]), "r"(a[3]), "r"(b[0]), "r"(b[1]));
}
// fp16 mma (projection)
__device__ __forceinline__ void mma16816h(float* c, const u32* a, const u32* b) {
    asm volatile("mma.sync.aligned.m16n8k16.row.col.f32.f16.f16.f32 "
        "{%0,%1,%2,%3}, {%4,%5,%6,%7}, {%8,%9}, {%0,%1,%2,%3};"
        : "+f"(c[0]), "+f"(c[1]), "+f"(c[2]), "+f"(c[3])
        : "r"(a[0]), "r"(a[1]), "r"(a[2]), "r"(a[3]), "r"(b[0]), "r"(b[1]));
}
// pack two fp32 -> bf16 pair (hi/lo split)
__device__ __forceinline__ void bfsplit2(float x0, float x1, u32& h, u32& l) {
    __nv_bfloat16 h0 = __float2bfloat16(x0);
    __nv_bfloat16 h1 = __float2bfloat16(x1);
    __nv_bfloat16 l0 = __float2bfloat16(x0 - __bfloat162float(h0));
    __nv_bfloat16 l1 = __float2bfloat16(x1 - __bfloat162float(h1));
    h = (u32)__bfloat16_as_ushort(h0) | ((u32)__bfloat16_as_ushort(h1) << 16);
    l = (u32)__bfloat16_as_ushort(l0) | ((u32)__bfloat16_as_ushort(l1) << 16);
}
// pack two fp32 -> fp16 pair
__device__ __forceinline__ u32 hpack2(float x0, float x1) {
    __half2 h = __floats2half2_rn(x0, x1);
    return *(u32*)&h;
}

// XOR-swizzled 64x64 bf16 tile: row*128B, 8 chunks of 16B, chunk ^= row&7.
#define SWZ(row, col) (((row) << 7) + (((((col) >> 3) ^ (row)) & 7) << 4) + (((col) & 7) << 1))

// ---------------------------------------------------------------------------
// Kernel: expand rpb_table via rel_index into [head][q][k]
// ---------------------------------------------------------------------------
__global__ void bias_kernel(const float* __restrict__ rpb, const int* __restrict__ rel) {
    int idx = blockIdx.x * blockDim.x + threadIdx.x;   // 32768
    if (idx >= NHEAD * 64 * 64) return;
    int h = idx >> 12;
    int r = idx & 4095;                                // q*64 + k
    g_bias[idx] = rpb[rel[r] * NHEAD + h];
}

// ---------------------------------------------------------------------------
// Kernel: convert W (fp32) -> fp16
// ---------------------------------------------------------------------------
__global__ void __launch_bounds__(256) wconv_kernel(const float* __restrict__ W) {
    int i = blockIdx.x * 256 + threadIdx.x;
    g_w16[i] = __float2half_rn(W[i]);
}

// ---------------------------------------------------------------------------
// Kernel: windowed cosine attention on mma.sync bf16 (hi/lo 3-term splits).
// Block = one (window, head), 128 threads / 4 warps; warp w = query rows 16w..
// qkv loaded via cp.async into fp32 staging [d][a]; bf16 tiles OVERLAY the
// staging region (read-to-regs -> sync -> write). q converts while k,v land.
// ---------------------------------------------------------------------------
// smem byte offsets (bf16 tiles overlay the fp32 staging exactly)
#define QH_O  0              // fp32 q staging = [0, 16384)
#define QL_O  8192
#define KH_O  16384          // fp32 k staging = [16384, 32768)
#define KL_O  24576
#define VH_O  32768          // fp32 v staging = [32768, 49152)
#define VL_O  40960
#define PSQ_O 49152          // 128 floats
#define PSK_O 49664          // 128 floats
#define QSV_O 50176          // 64 floats: 1/|q_row|
#define KSV_O 50432          // 64 floats: 1/|k_row|
#define ATTN_SMEM 50688

__global__ void __launch_bounds__(128, 4) attn_kernel(const float* __restrict__ qkv,
                                                      const float* __restrict__ lscale) {
    extern __shared__ char smem[];
    float* psq  = (float*)(smem + PSQ_O);
    float* psk  = (float*)(smem + PSK_O);
    float* qsv  = (float*)(smem + QSV_O);
    float* ksv  = (float*)(smem + KSV_O);

    const int tid  = threadIdx.x;
    const int lane = tid & 31;
    const int wrp  = tid >> 5;

    const int wh   = blockIdx.x;
    const int head = wh & 7;
    const int win  = wh >> 3;
    const int b    = win >> 8;
    const int wy   = (win >> 4) & 15;
    const int wx   = win & 15;

    const float* base = qkv + (size_t)b * (NHEAD * 192 * 16384)
                            + (size_t)head * (192 * 16384)
                            + wy * 8 * HW_ + wx * 8;

    const u32 sb = smem_u32(smem);

    // ---- issue all qkv loads as cp.async (3 groups: q, k, v) ----
    // chunk id: d = id>>4, ay = (id>>1)&7, hf = id&1; 16B per chunk.
    #pragma unroll
    for (int kind = 0; kind < 3; kind++) {
        #pragma unroll
        for (int j = 0; j < 8; j++) {
            int id = tid + j * 128;
            int d  = id >> 4;
            int ay = (id >> 1) & 7;
            int hf = id & 1;
            const float* src = base + (size_t)(kind * 64 + d) * 16384 + ay * HW_ + hf * 4;
            u32 dst = sb + kind * 16384 + (((d << 6) + (ay << 3) + (hf << 2)) << 2);
            cpa16(dst, src);
        }
        CPA_COMMIT();
    }

    const int a = tid & 63;
    const int half_ = tid >> 6;
    const int d0 = half_ * 32;
    float frs[32];

    // ---- q: wait own group, read staging col, overlay-write bf16 splits ----
    CPA_WAIT(2);
    __syncthreads();
    {
        const float* st = (const float*)smem;
        #pragma unroll
        for (int i = 0; i < 32; i++) frs[i] = st[(d0 + i) * 64 + a];
    }
    __syncthreads();
    {
        float ssq = 0.f;
        #pragma unroll
        for (int i = 0; i < 32; i += 2) {
            ssq += frs[i] * frs[i] + frs[i + 1] * frs[i + 1];
            u32 h_, l_;
            bfsplit2(frs[i], frs[i + 1], h_, l_);
            *(u32*)(smem + QH_O + SWZ(a, d0 + i)) = h_;
            *(u32*)(smem + QL_O + SWZ(a, d0 + i)) = l_;
        }
        psq[half_ * 64 + a] = ssq;
    }

    // ---- k ----
    CPA_WAIT(1);
    __syncthreads();
    {
        const float* st = (const float*)(smem + 16384);
        #pragma unroll
        for (int i = 0; i < 32; i++) frs[i] = st[(d0 + i) * 64 + a];
    }
    __syncthreads();
    {
        float ssk = 0.f;
        #pragma unroll
        for (int i = 0; i < 32; i += 2) {
            ssk += frs[i] * frs[i] + frs[i + 1] * frs[i + 1];
            u32 h_, l_;
            bfsplit2(frs[i], frs[i + 1], h_, l_);
            *(u32*)(smem + KH_O + SWZ(a, d0 + i)) = h_;
            *(u32*)(smem + KL_O + SWZ(a, d0 + i)) = l_;
        }
        psk[half_ * 64 + a] = ssk;
    }

    // ---- v ----
    CPA_WAIT(0);
    __syncthreads();
    {
        const float* st = (const float*)(smem + 32768);
        #pragma unroll
        for (int i = 0; i < 32; i++) frs[i] = st[(d0 + i) * 64 + a];
    }
    __syncthreads();
    {
        #pragma unroll
        for (int i = 0; i < 32; i += 2) {
            u32 h_, l_;
            bfsplit2(frs[i], frs[i + 1], h_, l_);
            *(u32*)(smem + VH_O + SWZ(a, d0 + i)) = h_;
            *(u32*)(smem + VL_O + SWZ(a, d0 + i)) = l_;
        }
    }
    __syncthreads();

    // ---- inverse norms ----
    if (tid < 64) {
        qsv[tid] = 1.0f / fmaxf(sqrtf(psq[tid] + psq[tid + 64]), 1e-12f);
    } else {
        int a2 = tid - 64;
        ksv[a2] = 1.0f / fmaxf(sqrtf(psk[a2] + psk[a2 + 64]), 1e-12f);
    }
    __syncthreads();

    const int m0 = wrp * 16;
    const int arow = m0 + (lane & 15);
    const int acol = (lane >> 4) * 8;
    const int brl  = lane & 7;
    const int bcl  = ((lane >> 3) & 1) * 8;
    const int trl  = lane & 15;

    const int r0 = m0 + (lane >> 2);
    const int cb = 2 * (lane & 3);

    // ---- prefetch bias fragments (L2-resident; hides under QK MMAs) ----
    float2 bf0[8], bf1[8];
    {
        const float2* gb = (const float2*)(g_bias + head * 4096);
        #pragma unroll
        for (int j = 0; j < 8; j++) {
            bf0[j] = gb[r0 * 32 + j * 4 + (lane & 3)];
            bf1[j] = gb[(r0 + 8) * 32 + j * 4 + (lane & 3)];
        }
    }

    // ---- S = QK^T, 3-term split ----
    float acc[8][4];
    #pragma unroll
    for (int j = 0; j < 8; j++)
        #pragma unroll
        for (int r = 0; r < 4; r++) acc[j][r] = 0.f;

    #pragma unroll
    for (int ks = 0; ks < 4; ks++) {
        const int kf = ks * 16;
        u32 aqh[4], aql[4];
        ldmx4(aqh, sb + QH_O + SWZ(arow, acol + kf));
        ldmx4(aql, sb + QL_O + SWZ(arow, acol + kf));
        #pragma unroll
        for (int j = 0; j < 8; j++) {
            u32 bkh[2], bkl[2];
            int krow = j * 8 + brl;
            ldmx2(bkh, sb + KH_O + SWZ(krow, bcl + kf));
            ldmx2(bkl, sb + KL_O + SWZ(krow, bcl + kf));
            mma16816(acc[j], aqh, bkh);
            mma16816(acc[j], aqh, bkl);
            mma16816(acc[j], aql, bkh);
        }
    }

    // ---- cosine scale + bias + softmax ----
    const float sc = __expf(fminf(lscale[head], 4.6051702f));
    const float f0 = sc * qsv[r0];
    const float f1 = sc * qsv[r0 + 8];
    #pragma unroll
    for (int j = 0; j < 8; j++) {
        int c = 8 * j + cb;
        float kc0 = ksv[c], kc1 = ksv[c + 1];
        acc[j][0] = acc[j][0] * f0 * kc0 + bf0[j].x;
        acc[j][1] = acc[j][1] * f0 * kc1 + bf0[j].y;
        acc[j][2] = acc[j][2] * f1 * kc0 + bf1[j].x;
        acc[j][3] = acc[j][3] * f1 * kc1 + bf1[j].y;
    }
    float mx0 = -1e30f, mx1 = -1e30f;
    #pragma unroll
    for (int j = 0; j < 8; j++) {
        mx0 = fmaxf(mx0, fmaxf(acc[j][0], acc[j][1]));
        mx1 = fmaxf(mx1, fmaxf(acc[j][2], acc[j][3]));
    }
    mx0 = fmaxf(mx0, __shfl_xor_sync(0xffffffffu, mx0, 1));
    mx0 = fmaxf(mx0, __shfl_xor_sync(0xffffffffu, mx0, 2));
    mx1 = fmaxf(mx1, __shfl_xor_sync(0xffffffffu, mx1, 1));
    mx1 = fmaxf(mx1, __shfl_xor_sync(0xffffffffu, mx1, 2));
    float s0 = 0.f, s1 = 0.f;
    #pragma unroll
    for (int j = 0; j < 8; j++) {
        acc[j][0] = __expf(acc[j][0] - mx0); s0 += acc[j][0];
        acc[j][1] = __expf(acc[j][1] - mx0); s0 += acc[j][1];
        acc[j][2] = __expf(acc[j][2] - mx1); s1 += acc[j][2];
        acc[j][3] = __expf(acc[j][3] - mx1); s1 += acc[j][3];
    }
    s0 += __shfl_xor_sync(0xffffffffu, s0, 1);
    s0 += __shfl_xor_sync(0xffffffffu, s0, 2);
    s1 += __shfl_xor_sync(0xffffffffu, s1, 1);
    s1 += __shfl_xor_sync(0xffffffffu, s1, 2);
    const float inv0 = 1.0f / s0, inv1 = 1.0f / s1;
    #pragma unroll
    for (int j = 0; j < 8; j++) {
        acc[j][0] *= inv0; acc[j][1] *= inv0;
        acc[j][2] *= inv1; acc[j][3] *= inv1;
    }

    // ---- repack P C-fragments as A-fragments ----
    u32 aph[4][4], apl[4][4];
    #pragma unroll
    for (int kk = 0; kk < 4; kk++) {
        bfsplit2(acc[2 * kk][0],     acc[2 * kk][1],     aph[kk][0], apl[kk][0]);
        bfsplit2(acc[2 * kk][2],     acc[2 * kk][3],     aph[kk][1], apl[kk][1]);
        bfsplit2(acc[2 * kk + 1][0], acc[2 * kk + 1][1], aph[kk][2], apl[kk][2]);
        bfsplit2(acc[2 * kk + 1][2], acc[2 * kk + 1][3], aph[kk][3], apl[kk][3]);
    }

    // ---- O = P.V, 3-term; V [a][d] read via ldmatrix.trans ----
    float o[8][4];
    #pragma unroll
    for (int j = 0; j < 8; j++)
        #pragma unroll
        for (int r = 0; r < 4; r++) o[j][r] = 0.f;

    #pragma unroll
    for (int ks = 0; ks < 4; ks++) {
        const int kf = ks * 16;
        #pragma unroll
        for (int jd = 0; jd < 8; jd++) {
            u32 bvh[2], bvl[2];
            u32 bo = SWZ(kf + trl, jd * 8);
            ldmx2t(bvh, sb + VH_O + bo);
            ldmx2t(bvl, sb + VL_O + bo);
            mma16816(o[jd], aph[ks], bvh);
            mma16816(o[jd], aph[ks], bvl);
            mma16816(o[jd], apl[ks], bvh);
        }
    }

    // ---- store O as fp16 to X [pixel][channel] ----
    const int pr0 = b * 16384 + (wy * 8 + (r0 >> 3)) * HW_ + wx * 8 + (r0 & 7);
    const int r1 = r0 + 8;
    const int pr1 = b * 16384 + (wy * 8 + (r1 >> 3)) * HW_ + wx * 8 + (r1 & 7);
    const size_t x0 = (size_t)pr0 * CCH + head * 64;
    const size_t x1 = (size_t)pr1 * CCH + head * 64;
    #pragma unroll
    for (int j = 0; j < 8; j++) {
        int c = 8 * j + cb;
        *(u32*)(g_xh + x0 + c) = hpack2(o[j][0], o[j][1]);
        *(u32*)(g_xh + x1 + c) = hpack2(o[j][2], o[j][3]);
    }
}

// ---------------------------------------------------------------------------
// Kernel: projection GEMM via mma.sync fp16, single term (W16 · X16).
// CTA: 128 channels (M) x 128 pixels (N), K=512 in 8 chunks of 64.
// ---------------------------------------------------------------------------
#define LDT2 72                      // 64 + 8 pad (fp16 units)
#define PTILE_B (128 * LDT2 * 2)     // 18432 bytes per tile
#define PSTG_B  (2 * PTILE_B)        // W | X = 36864
#define PROJ_SMEM (2 * PSTG_B)       // 73728 bytes

__device__ __forceinline__ void proj_load_stage(u32 sbase, int m0g, int n0g, int k0, int tid) {
    #pragma unroll
    for (int j = 0; j < 4; j++) {
        int id = tid + j * 256;          // 0..1023
        int r  = id >> 3;                // row 0..127
        int c  = (id & 7) * 8;           // col (fp16)
        u32 dst = sbase + 2 * (r * LDT2 + c);
        cpa16(dst,           g_w16 + (size_t)(m0g + r) * CCH + k0 + c);
        cpa16(dst + PTILE_B, g_xh  + (size_t)(n0g + r) * CCH + k0 + c);
    }
    CPA_COMMIT();
}

__global__ void __launch_bounds__(256) proj_hmma_kernel(const float* __restrict__ pb,
                                                        float* __restrict__ out) {
    extern __shared__ __half psm[];
    const int tid  = threadIdx.x;
    const int wid  = tid >> 5;
    const int lane = tid & 31;
    const int wm   = wid >> 2;
    const int wn   = wid & 3;

    const int m0g = blockIdx.x * 128;
    const int n0g = blockIdx.y * 128;

    const u32 sb = smem_u32(psm);

    float acc[4][4][4];
    #pragma unroll
    for (int i = 0; i < 4; i++)
        #pragma unroll
        for (int j = 0; j < 4; j++)
            #pragma unroll
            for (int r = 0; r < 4; r++) acc[i][j][r] = 0.f;

    proj_load_stage(sb,          m0g, n0g, 0,  tid);
    proj_load_stage(sb + PSTG_B, m0g, n0g, 64, tid);

    const int arow = wm * 64 + (lane & 15);
    const int acol = (lane >> 4) * 8;
    const int brow = wn * 32 + (lane & 7);
    const int bcol = ((lane >> 3) & 1) * 8;

    #pragma unroll 1
    for (int kc = 0; kc < 8; kc++) {
        const u32 stg = sb + (kc & 1) * PSTG_B;
        if (kc < 7) { CPA_WAIT(1); } else { CPA_WAIT(0); }
        __syncthreads();

        const u32 whb = stg;
        const u32 xhb = stg + PTILE_B;

        #pragma unroll
        for (int ks = 0; ks < 4; ks++) {
            const int kf = ks * 16;
            u32 ah[4][4], bh[4][2];
            #pragma unroll
            for (int i = 0; i < 4; i++)
                ldmx4(ah[i], whb + 2 * ((arow + i * 16) * LDT2 + acol + kf));
            #pragma unroll
            for (int j = 0; j < 4; j++)
                ldmx2(bh[j], xhb + 2 * ((brow + j * 8) * LDT2 + bcol + kf));
            #pragma unroll
            for (int i = 0; i < 4; i++)
                #pragma unroll
                for (int j = 0; j < 4; j++)
                    mma16816h(acc[i][j], ah[i], bh[j]);
        }
        __syncthreads();
        if (kc + 2 < 8) proj_load_stage(stg, m0g, n0g, (kc + 2) * 64, tid);
    }

    const int bb = n0g >> 14;
    const int hwb = (n0g & 16383) + wn * 32 + 2 * (lane & 3);
    #pragma unroll
    for (int i = 0; i < 4; i++) {
        int m = m0g + wm * 64 + i * 16 + (lane >> 2);
        float bias0 = pb[m];
        float bias8 = pb[m + 8];
        float* r0 = out + ((size_t)(bb * CCH + m)) * 16384 + hwb;
        float* r8 = out + ((size_t)(bb * CCH + m + 8)) * 16384 + hwb;
        #pragma unroll
        for (int j = 0; j < 4; j++) {
            float2 v0 = {acc[i][j][0] + bias0, acc[i][j][1] + bias0};
            float2 v1 = {acc[i][j][2] + bias8, acc[i][j][3] + bias8};
            *(float2*)(r0 + j * 8) = v0;
            *(float2*)(r8 + j * 8) = v1;
        }
    }
}

// ---------------------------------------------------------------------------
extern "C" void kernel_launch(void* const* d_in, const int* in_sizes, int n_in,
                              void* d_out, int out_size) {
    const float* qkv = (const float*)d_in[0];   // (4, 8, 192, 128, 128) f32
    const float* lsc = (const float*)d_in[1];   // (8,1,1) f32
    const float* rpb = (const float*)d_in[2];   // (225, 8) f32
    const float* pw  = (const float*)d_in[3];   // (512, 512) f32
    const float* pb  = (const float*)d_in[4];   // (512,) f32
    const int*   rel = (const int*)d_in[5];     // (64, 64) i32
    float* out = (float*)d_out;                 // (4, 512, 128, 128) f32

    cudaFuncSetAttribute(attn_kernel,
                         cudaFuncAttributeMaxDynamicSharedMemorySize, ATTN_SMEM);
    cudaFuncSetAttribute(proj_hmma_kernel,
                         cudaFuncAttributeMaxDynamicSharedMemorySize, PROJ_SMEM);

    bias_kernel<<<NHEAD * 64 * 64 / 256, 256>>>(rpb, rel);
    wconv_kernel<<<CCH * CCH / 256, 256>>>(pw);
    attn_kernel<<<1024 * NHEAD, 128, ATTN_SMEM>>>(qkv, lsc);
    proj_hmma_kernel<<<dim3(CCH / 128, NPIX / 128), 256, PROJ_SMEM>>>(pb, out);
}